// round 1
// baseline (speedup 1.0000x reference)
#include <cuda_runtime.h>
#include <math.h>

#define S   2048
#define DIM 1024
#define H   16
#define HD  64

// ---------------- scratch (__device__ globals: allocation-free) ----------------
__device__ float g_qr[S*DIM];
__device__ float g_kr[S*DIM];
__device__ float g_vr[S*DIM];
__device__ float g_qi[S*DIM];
__device__ float g_ki[S*DIM];
__device__ float g_vi[S*DIM];
__device__ float g_Qc[H*S*128];   // [h][s][qr|qi]
__device__ float g_KR[H*S*128];   // [h][s][kr|-ki]
__device__ float g_KI[H*S*128];   // [h][s][ki| kr]
__device__ float g_Vc[H*S*128];   // [h][s][vr| vi]
__device__ float g_scores[(size_t)H*S*S];   // 256 MB
__device__ float g_attn[2*S*DIM];           // attention outputs (r then i)

__device__ __forceinline__ float neg_inf() { return __int_as_float(0xff800000); }

// ---------------- batched GEMM+bias: C = A·Wᵀ + b ----------------
// A: [M,K] row-major, W: [N,K] row-major, C: [M,N]. M=2048,N=K=1024.
struct GemmArgs {
    const float* A[8];
    const float* W[8];
    const float* Bv[8];
    float*       C[8];
};

__global__ __launch_bounds__(256, 2)
void gemm_bias_kernel(GemmArgs ga, int M, int N, int K)
{
    const int z = blockIdx.z;
    const float* __restrict__ A  = ga.A[z];
    const float* __restrict__ W  = ga.W[z];
    const float* __restrict__ Bb = ga.Bv[z];
    float* __restrict__       C  = ga.C[z];

    const int BM = 128, BN = 128, BK = 16;
    __shared__ float As[BK][BM + 4];   // stride 132 (float4-aligned, conflict-reduced)
    __shared__ float Bs[BK][BN + 4];

    const int tid = threadIdx.x;
    const int m0  = blockIdx.y * BM;
    const int n0  = blockIdx.x * BN;
    const int tm  = (tid >> 4) * 8;
    const int tn  = (tid & 15) * 8;

    float acc[8][8];
#pragma unroll
    for (int i = 0; i < 8; i++)
#pragma unroll
        for (int j = 0; j < 8; j++) acc[i][j] = 0.f;

    for (int k0 = 0; k0 < K; k0 += BK) {
#pragma unroll
        for (int i = 0; i < 2; i++) {
            int idx = tid + i * 256;          // 0..511
            int row = idx >> 2;               // 0..127
            int kv  = (idx & 3) * 4;          // 0,4,8,12
            float4 a4 = *(const float4*)&A[(size_t)(m0 + row) * K + k0 + kv];
            As[kv + 0][row] = a4.x; As[kv + 1][row] = a4.y;
            As[kv + 2][row] = a4.z; As[kv + 3][row] = a4.w;
            float4 b4 = *(const float4*)&W[(size_t)(n0 + row) * K + k0 + kv];
            Bs[kv + 0][row] = b4.x; Bs[kv + 1][row] = b4.y;
            Bs[kv + 2][row] = b4.z; Bs[kv + 3][row] = b4.w;
        }
        __syncthreads();
#pragma unroll
        for (int kk = 0; kk < BK; kk++) {
            float a[8], b[8];
            *(float4*)&a[0] = *(const float4*)&As[kk][tm];
            *(float4*)&a[4] = *(const float4*)&As[kk][tm + 4];
            *(float4*)&b[0] = *(const float4*)&Bs[kk][tn];
            *(float4*)&b[4] = *(const float4*)&Bs[kk][tn + 4];
#pragma unroll
            for (int i = 0; i < 8; i++)
#pragma unroll
                for (int j = 0; j < 8; j++)
                    acc[i][j] = fmaf(a[i], b[j], acc[i][j]);
        }
        __syncthreads();
    }

#pragma unroll
    for (int i = 0; i < 8; i++) {
        float* crow = C + (size_t)(m0 + tm + i) * N + n0 + tn;
#pragma unroll
        for (int j = 0; j < 8; j += 4) {
            float4 bv = *(const float4*)&Bb[n0 + tn + j];
            float4 o;
            o.x = acc[i][j + 0] + bv.x;
            o.y = acc[i][j + 1] + bv.y;
            o.z = acc[i][j + 2] + bv.z;
            o.w = acc[i][j + 3] + bv.w;
            *(float4*)&crow[j] = o;
        }
    }
}

// ---------------- RoPE (in place on q_r,k_r,q_i,k_i) ----------------
__global__ void rope_kernel(float* q1, float* k1, float* q2, float* k2,
                            const float* __restrict__ freqs)
{
    int idx = blockIdx.x * 256 + threadIdx.x;       // S*H*16 threads
    int j  = idx & 15;
    int hh = (idx >> 4) & 15;
    int s  = idx >> 8;
    float ang = (float)s * freqs[j];
    float sn, cs;
    sincosf(ang, &sn, &cs);
    size_t base = (size_t)s * DIM + hh * HD + 2 * j;
    float a, b;
    a = q1[base]; b = q1[base + 1];
    q1[base] = a * cs - b * sn; q1[base + 1] = a * sn + b * cs;
    a = k1[base]; b = k1[base + 1];
    k1[base] = a * cs - b * sn; k1[base + 1] = a * sn + b * cs;
    a = q2[base]; b = q2[base + 1];
    q2[base] = a * cs - b * sn; q2[base + 1] = a * sn + b * cs;
    a = k2[base]; b = k2[base + 1];
    k2[base] = a * cs - b * sn; k2[base + 1] = a * sn + b * cs;
}

// ---------------- V pack: Vcat[h][s][0:64]=v_r, [64:128]=v_i ----------------
__global__ void pack_v_kernel(const float* __restrict__ vr,
                              const float* __restrict__ vi,
                              float* __restrict__ Vc)
{
    int idx = blockIdx.x * 256 + threadIdx.x;     // H*S*128 threads
    int c  = idx & 127;
    int sh = idx >> 7;                            // h*S + s
    int s  = sh & (S - 1);
    int hh = sh >> 11;
    float v = (c < HD) ? vr[(size_t)s * DIM + hh * HD + c]
                       : vi[(size_t)s * DIM + hh * HD + (c - HD)];
    Vc[idx] = v;
}

// ---------------- entanglement mix + phase rotation + cat packing ----------------
__global__ void entangle_kernel(const float* __restrict__ qr, const float* __restrict__ qi,
                                const float* __restrict__ kr, const float* __restrict__ ki,
                                const float* __restrict__ ent, const float* __restrict__ phase,
                                float* __restrict__ Qc, float* __restrict__ KR,
                                float* __restrict__ KI)
{
    int s = blockIdx.x;
    __shared__ float sqr[DIM], sqi[DIM], skr[DIM], ski[DIM];
    __shared__ float sent[H * H];
    int tid = threadIdx.x;
    if (tid < H * H) sent[tid] = ent[tid];
    for (int i = tid; i < DIM; i += 256) {
        size_t o = (size_t)s * DIM + i;
        sqr[i] = qr[o]; sqi[i] = qi[o]; skr[i] = kr[o]; ski[i] = ki[o];
    }
    __syncthreads();
    for (int p = tid; p < DIM; p += 256) {
        int x = p >> 6, d = p & 63;
        float aqr = 0.f, aqi = 0.f, akr = 0.f, aki = 0.f;
#pragma unroll
        for (int h2 = 0; h2 < H; h2++) {
            float e = sent[h2 * H + x];
            int o = h2 * HD + d;
            aqr = fmaf(sqr[o], e, aqr);
            aqi = fmaf(sqi[o], e, aqi);
            akr = fmaf(skr[o], e, akr);
            aki = fmaf(ski[o], e, aki);
        }
        float pv = phase[p];
        float ps, pc;
        sincosf(pv, &ps, &pc);
        float qr2 = aqr * pc - aqi * ps;
        float qi2 = aqr * ps + aqi * pc;
        float kr2 = akr * pc - aki * ps;
        float ki2 = akr * ps + aki * pc;
        size_t base = ((size_t)x * S + s) * 128;
        Qc[base + d]      = qr2;  Qc[base + HD + d] = qi2;
        KR[base + d]      = kr2;  KR[base + HD + d] = -ki2;
        KI[base + d]      = ki2;  KI[base + HD + d] = kr2;
    }
}

// ---------------- scores: mag epilogue, causal tiles only ----------------
__global__ __launch_bounds__(256, 2)
void scores_kernel(const float* __restrict__ Qc, const float* __restrict__ KRc,
                   const float* __restrict__ KIc,
                   const float* __restrict__ sc_is, const float* __restrict__ sc_at,
                   const float* __restrict__ sc_ce, float* __restrict__ mag)
{
    int h   = blockIdx.y;
    int lin = blockIdx.x;                        // 0..527, lower-tri tile index
    int ti  = (int)((sqrtf(8.f * lin + 1.f) - 1.f) * 0.5f);
    while ((ti + 1) * (ti + 2) / 2 <= lin) ++ti;
    while (ti * (ti + 1) / 2 > lin) --ti;
    int tj  = lin - ti * (ti + 1) / 2;
    int m0 = ti * 64, n0 = tj * 64;

    __shared__ float Qs[32][68];
    __shared__ float Rs[32][68];
    __shared__ float Is[32][68];

    int tid = threadIdx.x;
    int tm = (tid >> 4) * 4, tn = (tid & 15) * 4;
    float accr[4][4], acci[4][4];
#pragma unroll
    for (int i = 0; i < 4; i++)
#pragma unroll
        for (int j = 0; j < 4; j++) { accr[i][j] = 0.f; acci[i][j] = 0.f; }

    const float* qb = Qc  + ((size_t)h * S + m0) * 128;
    const float* rb = KRc + ((size_t)h * S + n0) * 128;
    const float* ib = KIc + ((size_t)h * S + n0) * 128;

    for (int k0 = 0; k0 < 128; k0 += 32) {
#pragma unroll
        for (int i = 0; i < 2; i++) {
            int idx = tid + i * 256;     // 0..511
            int row = idx >> 3;          // 0..63
            int kv  = (idx & 7) * 4;     // 0..28
            float4 q4 = *(const float4*)(qb + (size_t)row * 128 + k0 + kv);
            Qs[kv + 0][row] = q4.x; Qs[kv + 1][row] = q4.y;
            Qs[kv + 2][row] = q4.z; Qs[kv + 3][row] = q4.w;
            float4 r4 = *(const float4*)(rb + (size_t)row * 128 + k0 + kv);
            Rs[kv + 0][row] = r4.x; Rs[kv + 1][row] = r4.y;
            Rs[kv + 2][row] = r4.z; Rs[kv + 3][row] = r4.w;
            float4 i4 = *(const float4*)(ib + (size_t)row * 128 + k0 + kv);
            Is[kv + 0][row] = i4.x; Is[kv + 1][row] = i4.y;
            Is[kv + 2][row] = i4.z; Is[kv + 3][row] = i4.w;
        }
        __syncthreads();
#pragma unroll
        for (int kk = 0; kk < 32; kk++) {
            float a[4], br[4], bi[4];
            *(float4*)a  = *(const float4*)&Qs[kk][tm];
            *(float4*)br = *(const float4*)&Rs[kk][tn];
            *(float4*)bi = *(const float4*)&Is[kk][tn];
#pragma unroll
            for (int i = 0; i < 4; i++)
#pragma unroll
                for (int j = 0; j < 4; j++) {
                    accr[i][j] = fmaf(a[i], br[j], accr[i][j]);
                    acci[i][j] = fmaf(a[i], bi[j], acci[i][j]);
                }
        }
        __syncthreads();
    }

    float strength = 1.0f / (1.0f + expf(-*sc_is));
    float temp     = fmaxf(expf(*sc_at), 0.1f);
    float eps      = 0.03f / (1.0f + expf(-*sc_ce));
    float factor   = strength / temp;
    const float scale = 0.125f;   // 1/sqrt(64)

    float* out = mag + (size_t)h * S * S;
#pragma unroll
    for (int i = 0; i < 4; i++) {
        int s = m0 + tm + i;
#pragma unroll
        for (int j = 0; j < 4; j++) {
            int t = n0 + tn + j;
            float r  = accr[i][j] * scale;
            float im = acci[i][j] * scale;
            float ar = r + eps * im;
            float ai = im - eps * r;
            float m  = sqrtf(ar * ar + ai * ai + 1e-6f);
            out[(size_t)s * S + t] = (t <= s) ? m * factor : neg_inf();
        }
    }
}

// ---------------- row softmax (single-read, register resident) ----------------
__global__ void softmax_kernel(float* __restrict__ p)
{
    __shared__ float sm[8];
    int row = blockIdx.x;                  // h*S + s
    int s   = row & (S - 1);
    int L   = ((s >> 6) + 1) << 6;         // process to 64-tile end (masked entries are -inf)
    float* ptr = p + (size_t)row * S;
    int tid = threadIdx.x;

    float vals[8];
    float mx = neg_inf();
    int n = 0;
    for (int i = tid; i < L; i += 256) {
        float v = ptr[i];
        vals[n++] = v;
        mx = fmaxf(mx, v);
    }
#pragma unroll
    for (int o = 16; o > 0; o >>= 1) mx = fmaxf(mx, __shfl_xor_sync(0xffffffffu, mx, o));
    if ((tid & 31) == 0) sm[tid >> 5] = mx;
    __syncthreads();
    float tmx = sm[0];
#pragma unroll
    for (int i = 1; i < 8; i++) tmx = fmaxf(tmx, sm[i]);
    __syncthreads();

    float sum = 0.f;
    for (int k = 0; k < n; k++) {
        vals[k] = expf(vals[k] - tmx);     // expf(-inf)=0 handles the mask
        sum += vals[k];
    }
#pragma unroll
    for (int o = 16; o > 0; o >>= 1) sum += __shfl_xor_sync(0xffffffffu, sum, o);
    if ((tid & 31) == 0) sm[tid >> 5] = sum;
    __syncthreads();
    float tsum = 0.f;
#pragma unroll
    for (int i = 0; i < 8; i++) tsum += sm[i];

    float inv = 1.0f / tsum;
    n = 0;
    for (int i = tid; i < L; i += 256) ptr[i] = vals[n++] * inv;
}

// ---------------- P·Vcat (causal K range) ----------------
__global__ __launch_bounds__(256, 2)
void pv_kernel(const float* __restrict__ p, const float* __restrict__ Vc,
               float* __restrict__ outc)
{
    int h  = blockIdx.y;
    int ti = blockIdx.x;
    int m0 = ti * 64;

    __shared__ float Ps[32][68];
    __shared__ float Vs[32][132];

    int tid = threadIdx.x;
    int tm = (tid >> 4) * 4;        // 4 rows
    int tn = (tid & 15) * 8;        // 8 cols of 128
    float acc[4][8];
#pragma unroll
    for (int i = 0; i < 4; i++)
#pragma unroll
        for (int j = 0; j < 8; j++) acc[i][j] = 0.f;

    const float* prow  = p  + ((size_t)h * S + m0) * S;
    const float* vbase = Vc + (size_t)h * S * 128;
    int kend = (ti + 1) * 64;

    for (int t0 = 0; t0 < kend; t0 += 32) {
#pragma unroll
        for (int i = 0; i < 2; i++) {
            int idx = tid + i * 256;
            int row = idx >> 3;          // 0..63
            int kv  = (idx & 7) * 4;
            float4 p4 = *(const float4*)(prow + (size_t)row * S + t0 + kv);
            Ps[kv + 0][row] = p4.x; Ps[kv + 1][row] = p4.y;
            Ps[kv + 2][row] = p4.z; Ps[kv + 3][row] = p4.w;
        }
#pragma unroll
        for (int i = 0; i < 4; i++) {
            int idx = tid + i * 256;     // 0..1023
            int row = idx >> 5;          // 0..31
            int cv  = (idx & 31) * 4;
            float4 v4 = *(const float4*)(vbase + (size_t)(t0 + row) * 128 + cv);
            *(float4*)&Vs[row][cv] = v4;
        }
        __syncthreads();
#pragma unroll
        for (int kk = 0; kk < 32; kk++) {
            float a[4], b[8];
            *(float4*)a = *(const float4*)&Ps[kk][tm];
            *(float4*)&b[0] = *(const float4*)&Vs[kk][tn];
            *(float4*)&b[4] = *(const float4*)&Vs[kk][tn + 4];
#pragma unroll
            for (int i = 0; i < 4; i++)
#pragma unroll
                for (int j = 0; j < 8; j++)
                    acc[i][j] = fmaf(a[i], b[j], acc[i][j]);
        }
        __syncthreads();
    }

    // write: col<64 -> out_r plane, col>=64 -> out_i plane (tn is a multiple of 8)
    float* dst = (tn < HD) ? outc : outc + (size_t)S * DIM;
    int d0 = tn & 63;
#pragma unroll
    for (int i = 0; i < 4; i++) {
        int s = m0 + tm + i;
        float* crow = dst + (size_t)s * DIM + h * HD + d0;
        *(float4*)&crow[0] = *(float4*)&acc[i][0];
        *(float4*)&crow[4] = *(float4*)&acc[i][4];
    }
}

// ---------------- host ----------------
extern "C" void kernel_launch(void* const* d_in, const int* in_sizes, int n_in,
                              void* d_out, int out_size)
{
    const float* real  = (const float*)d_in[0];
    const float* imag  = (const float*)d_in[1];
    const float* Wq_r  = (const float*)d_in[2];
    const float* bq_r  = (const float*)d_in[3];
    const float* Wk_r  = (const float*)d_in[4];
    const float* bk_r  = (const float*)d_in[5];
    const float* Wv_r  = (const float*)d_in[6];
    const float* bv_r  = (const float*)d_in[7];
    const float* Wq_i  = (const float*)d_in[8];
    const float* bq_i  = (const float*)d_in[9];
    const float* Wk_i  = (const float*)d_in[10];
    const float* bk_i  = (const float*)d_in[11];
    const float* Wv_i  = (const float*)d_in[12];
    const float* bv_i  = (const float*)d_in[13];
    const float* Wo_r  = (const float*)d_in[14];
    const float* bo_r  = (const float*)d_in[15];
    const float* Wo_i  = (const float*)d_in[16];
    const float* bo_i  = (const float*)d_in[17];
    const float* phase = (const float*)d_in[18];
    const float* ent   = (const float*)d_in[19];
    const float* rfreq = (const float*)d_in[20];
    const float* s_is  = (const float*)d_in[21];
    const float* s_at  = (const float*)d_in[22];
    const float* s_ce  = (const float*)d_in[23];

    float *qr, *kr, *vr, *qi, *ki, *vi, *Qc, *KR, *KI, *Vc, *scores, *attn;
    cudaGetSymbolAddress((void**)&qr, g_qr);
    cudaGetSymbolAddress((void**)&kr, g_kr);
    cudaGetSymbolAddress((void**)&vr, g_vr);
    cudaGetSymbolAddress((void**)&qi, g_qi);
    cudaGetSymbolAddress((void**)&ki, g_ki);
    cudaGetSymbolAddress((void**)&vi, g_vi);
    cudaGetSymbolAddress((void**)&Qc, g_Qc);
    cudaGetSymbolAddress((void**)&KR, g_KR);
    cudaGetSymbolAddress((void**)&KI, g_KI);
    cudaGetSymbolAddress((void**)&Vc, g_Vc);
    cudaGetSymbolAddress((void**)&scores, g_scores);
    cudaGetSymbolAddress((void**)&attn, g_attn);

    float* out = (float*)d_out;

    // 1) six input projections in one batched launch
    GemmArgs gp = {};
    gp.A[0] = real; gp.W[0] = Wq_r; gp.Bv[0] = bq_r; gp.C[0] = qr;
    gp.A[1] = real; gp.W[1] = Wk_r; gp.Bv[1] = bk_r; gp.C[1] = kr;
    gp.A[2] = real; gp.W[2] = Wv_r; gp.Bv[2] = bv_r; gp.C[2] = vr;
    gp.A[3] = imag; gp.W[3] = Wq_i; gp.Bv[3] = bq_i; gp.C[3] = qi;
    gp.A[4] = imag; gp.W[4] = Wk_i; gp.Bv[4] = bk_i; gp.C[4] = ki;
    gp.A[5] = imag; gp.W[5] = Wv_i; gp.Bv[5] = bv_i; gp.C[5] = vi;
    gemm_bias_kernel<<<dim3(DIM / 128, S / 128, 6), 256>>>(gp, S, DIM, DIM);

    // 2) RoPE on q_r, k_r, q_i, k_i
    rope_kernel<<<(S * H * 16) / 256, 256>>>(qr, kr, qi, ki, rfreq);

    // 3) pack V
    pack_v_kernel<<<(H * S * 128) / 256, 256>>>(vr, vi, Vc);

    // 4) entanglement + phase, emit Qcat/KRcat/KIcat
    entangle_kernel<<<S, 256>>>(qr, qi, kr, ki, ent, phase, Qc, KR, KI);

    // 5) causal score magnitudes (528 lower-tri 64x64 tiles per head)
    scores_kernel<<<dim3(528, H), 256>>>(Qc, KR, KI, s_is, s_at, s_ce, scores);

    // 6) softmax per row
    softmax_kernel<<<H * S, 256>>>(scores);

    // 7) attention output (both r and i via Vcat)
    pv_kernel<<<dim3(S / 64, H), 256>>>(scores, Vc, attn);

    // 8) two output projections
    GemmArgs go = {};
    go.A[0] = attn;               go.W[0] = Wo_r; go.Bv[0] = bo_r; go.C[0] = out;
    go.A[1] = attn + (size_t)S * DIM; go.W[1] = Wo_i; go.Bv[1] = bo_i; go.C[1] = out + (size_t)S * DIM;
    gemm_bias_kernel<<<dim3(DIM / 128, S / 128, 2), 256>>>(go, S, DIM, DIM);
}

// round 3
// speedup vs baseline: 1.3290x; 1.3290x over previous
#include <cuda_runtime.h>
#include <cuda_bf16.h>
#include <math.h>
#include <stdint.h>

#define S   2048
#define DIM 1024
#define H   16
#define HD  64

// ---------------- scratch (__device__ globals: allocation-free) ----------------
__device__ float g_qr[S*DIM];
__device__ float g_kr[S*DIM];
__device__ float g_vr[S*DIM];
__device__ float g_qi[S*DIM];
__device__ float g_ki[S*DIM];
__device__ float g_vi[S*DIM];
__device__ float g_Qc[H*S*128];   // [h][s][qr|qi]
__device__ float g_KR[H*S*128];   // [h][s][kr|-ki]
__device__ float g_KI[H*S*128];   // [h][s][ki| kr]
__device__ float g_Vc[H*S*128];   // [h][s][vr| vi]
__device__ float g_scores[(size_t)H*S*S];   // 256 MB
__device__ float g_attn[2*S*DIM];           // attention outputs (r then i)

// bf16 split planes
__device__ __nv_bfloat16 g_real_hi[S*DIM],  g_real_lo[S*DIM];
__device__ __nv_bfloat16 g_imag_hi[S*DIM],  g_imag_lo[S*DIM];
__device__ __nv_bfloat16 g_W_hi[6*DIM*DIM], g_W_lo[6*DIM*DIM];
__device__ __nv_bfloat16 g_Wo_hi[2*DIM*DIM], g_Wo_lo[2*DIM*DIM];
__device__ __nv_bfloat16 g_attn_hi[2*S*DIM], g_attn_lo[2*S*DIM];

__device__ __forceinline__ float neg_inf() { return __int_as_float(0xff800000); }

__device__ __forceinline__ uint32_t smem_to_u32(const void* smem_ptr) {
    uint32_t addr;
    asm("{ .reg .u64 tmp; cvta.to.shared.u64 tmp, %1; cvt.u32.u64 %0, tmp; }"
        : "=r"(addr) : "l"(smem_ptr));
    return addr;
}
__device__ __forceinline__ void ldm_x4(uint32_t* r, uint32_t addr) {
    asm volatile("ldmatrix.sync.aligned.m8n8.x4.shared.b16 {%0,%1,%2,%3}, [%4];"
        : "=r"(r[0]), "=r"(r[1]), "=r"(r[2]), "=r"(r[3]) : "r"(addr));
}
__device__ __forceinline__ void mma_bf16(float* c, const uint32_t* a,
                                         uint32_t b0, uint32_t b1) {
    asm volatile("mma.sync.aligned.m16n8k16.row.col.f32.bf16.bf16.f32 "
        "{%0,%1,%2,%3}, {%4,%5,%6,%7}, {%8,%9}, {%0,%1,%2,%3};"
        : "+f"(c[0]), "+f"(c[1]), "+f"(c[2]), "+f"(c[3])
        : "r"(a[0]), "r"(a[1]), "r"(a[2]), "r"(a[3]), "r"(b0), "r"(b1));
}
__device__ __forceinline__ void cp16(uint32_t dst, const void* src) {
    asm volatile("cp.async.cg.shared.global [%0], [%1], 16;" :: "r"(dst), "l"(src));
}
__device__ __forceinline__ void cp_commit() {
    asm volatile("cp.async.commit_group;" ::: "memory");
}
template<int N> __device__ __forceinline__ void cp_wait() {
    asm volatile("cp.async.wait_group %0;" :: "n"(N) : "memory");
}

// SW128-style swizzle within a [128 rows x 64 bf16] plane (128B rows, 8 chunks)
__device__ __forceinline__ uint32_t swz(int r, int c) {
    return (uint32_t)(r * 128 + ((c ^ (r & 7)) << 4));
}

// ---------------- fp32 -> (hi, lo) bf16 split ----------------
__global__ void split_kernel(const float* __restrict__ x,
                             __nv_bfloat16* __restrict__ hi,
                             __nv_bfloat16* __restrict__ lo, int n4)
{
    int i = blockIdx.x * 256 + threadIdx.x;
    if (i >= n4) return;
    float4 v = ((const float4*)x)[i];
    __nv_bfloat16 h0 = __float2bfloat16(v.x);
    __nv_bfloat16 h1 = __float2bfloat16(v.y);
    __nv_bfloat16 h2 = __float2bfloat16(v.z);
    __nv_bfloat16 h3 = __float2bfloat16(v.w);
    __nv_bfloat162 hA; hA.x = h0; hA.y = h1;
    __nv_bfloat162 hB; hB.x = h2; hB.y = h3;
    ((__nv_bfloat162*)hi)[2*i]   = hA;
    ((__nv_bfloat162*)hi)[2*i+1] = hB;
    __nv_bfloat162 lA, lB;
    lA.x = __float2bfloat16(v.x - __bfloat162float(h0));
    lA.y = __float2bfloat16(v.y - __bfloat162float(h1));
    lB.x = __float2bfloat16(v.z - __bfloat162float(h2));
    lB.y = __float2bfloat16(v.w - __bfloat162float(h3));
    ((__nv_bfloat162*)lo)[2*i]   = lA;
    ((__nv_bfloat162*)lo)[2*i+1] = lB;
}

// ---------------- batched mma.sync GEMM: C = A·Bᵀ + bias (bf16x3) ----------------
// A: [M,K] row-major (hi/lo), B: [N,K] row-major (hi/lo), C fp32 [M,N].
struct MMArgs {
    const __nv_bfloat16* Ahi[8];
    const __nv_bfloat16* Alo[8];
    const __nv_bfloat16* Bhi[8];
    const __nv_bfloat16* Blo[8];
    const float*         bias[8];
    float*               C[8];
};

// SMEM stage layout: Ahi@0, Alo@16K, Bhi@32K, Blo@48K; stage stride 64K; 2 stages.
#define MM_STAGE 65536u

__global__ __launch_bounds__(256, 1)
void mm_bf16x3_kernel(MMArgs ga, int M, int N, int K)
{
    extern __shared__ __align__(1024) char smem[];
    const int z = blockIdx.z;
    const __nv_bfloat16* __restrict__ Ahi = ga.Ahi[z];
    const __nv_bfloat16* __restrict__ Alo = ga.Alo[z];
    const __nv_bfloat16* __restrict__ Bhi = ga.Bhi[z];
    const __nv_bfloat16* __restrict__ Blo = ga.Blo[z];
    const float* __restrict__ bias = ga.bias[z];
    float* __restrict__       C    = ga.C[z];

    const int m0 = blockIdx.y * 128;
    const int n0 = blockIdx.x * 128;

    const int tid  = threadIdx.x;
    const int lane = tid & 31;
    const int wid  = tid >> 5;
    const int wm   = (wid & 1) * 64;    // warp m-offset within CTA tile
    const int wn   = (wid >> 1) * 32;   // warp n-offset

    uint32_t sb = smem_to_u32(smem);

    float acc[4][4][4];
#pragma unroll
    for (int a = 0; a < 4; a++)
#pragma unroll
        for (int b = 0; b < 4; b++)
#pragma unroll
            for (int c = 0; c < 4; c++) acc[a][b][c] = 0.f;

    const int NIT = K / 64;

    // stage fill via cp.async: 4 planes x 1024 16B-chunks
    auto fill = [&](int it, int buf) {
        int k0 = it * 64;
        uint32_t so = sb + buf * MM_STAGE;
#pragma unroll
        for (int i = 0; i < 4; i++) {
            int q = tid + i * 256;          // 0..1023
            int r = q >> 3, c = q & 7;
            uint32_t off = swz(r, c);
            const __nv_bfloat16* pa = Ahi + (size_t)(m0 + r) * K + k0 + c * 8;
            const __nv_bfloat16* pl = Alo + (size_t)(m0 + r) * K + k0 + c * 8;
            const __nv_bfloat16* pb = Bhi + (size_t)(n0 + r) * K + k0 + c * 8;
            const __nv_bfloat16* pc = Blo + (size_t)(n0 + r) * K + k0 + c * 8;
            cp16(so +          off, pa);
            cp16(so + 16384u + off, pl);
            cp16(so + 32768u + off, pb);
            cp16(so + 49152u + off, pc);
        }
    };

    fill(0, 0);
    cp_commit();

    for (int it = 0; it < NIT; it++) {
        if (it + 1 < NIT) { fill(it + 1, (it + 1) & 1); cp_commit(); cp_wait<1>(); }
        else              { cp_wait<0>(); }
        __syncthreads();

        uint32_t so = sb + (uint32_t)(it & 1) * MM_STAGE;
#pragma unroll
        for (int kk = 0; kk < 64; kk += 16) {
            int ck = kk >> 3;
            uint32_t ah[4][4], al[4][4];
#pragma unroll
            for (int mt = 0; mt < 4; mt++) {
                int r = wm + mt * 16 + (lane & 15);
                int c = ck + (lane >> 4);
                uint32_t off = swz(r, c);
                ldm_x4(ah[mt], so + off);
                ldm_x4(al[mt], so + 16384u + off);
            }
            uint32_t bh[2][4], bl[2][4];
#pragma unroll
            for (int p = 0; p < 2; p++) {
                int r = wn + p * 16 + (lane & 7) + ((lane >> 4) << 3);
                int c = ck + ((lane >> 3) & 1);
                uint32_t off = swz(r, c);
                ldm_x4(bh[p], so + 32768u + off);
                ldm_x4(bl[p], so + 49152u + off);
            }
#pragma unroll
            for (int mt = 0; mt < 4; mt++)
#pragma unroll
                for (int nt = 0; nt < 4; nt++) {
                    uint32_t b0h = bh[nt >> 1][(nt & 1) * 2];
                    uint32_t b1h = bh[nt >> 1][(nt & 1) * 2 + 1];
                    uint32_t b0l = bl[nt >> 1][(nt & 1) * 2];
                    uint32_t b1l = bl[nt >> 1][(nt & 1) * 2 + 1];
                    mma_bf16(acc[mt][nt], ah[mt], b0h, b1h);
                    mma_bf16(acc[mt][nt], ah[mt], b0l, b1l);
                    mma_bf16(acc[mt][nt], al[mt], b0h, b1h);
                }
        }
        __syncthreads();
    }

    // epilogue: bias + store
#pragma unroll
    for (int mt = 0; mt < 4; mt++) {
        int m = m0 + wm + mt * 16 + (lane >> 2);
#pragma unroll
        for (int nt = 0; nt < 4; nt++) {
            int n = n0 + wn + nt * 8 + (lane & 3) * 2;
            float2 bv = *(const float2*)(bias + n);
            float2 o0, o1;
            o0.x = acc[mt][nt][0] + bv.x;
            o0.y = acc[mt][nt][1] + bv.y;
            o1.x = acc[mt][nt][2] + bv.x;
            o1.y = acc[mt][nt][3] + bv.y;
            *(float2*)(C + (size_t)m * N + n)       = o0;
            *(float2*)(C + (size_t)(m + 8) * N + n) = o1;
        }
    }
}

// ---------------- RoPE (in place on q_r,k_r,q_i,k_i) ----------------
__global__ void rope_kernel(float* q1, float* k1, float* q2, float* k2,
                            const float* __restrict__ freqs)
{
    int idx = blockIdx.x * 256 + threadIdx.x;       // S*H*16 threads
    int j  = idx & 15;
    int hh = (idx >> 4) & 15;
    int s  = idx >> 8;
    float ang = (float)s * freqs[j];
    float sn, cs;
    sincosf(ang, &sn, &cs);
    size_t base = (size_t)s * DIM + hh * HD + 2 * j;
    float a, b;
    a = q1[base]; b = q1[base + 1];
    q1[base] = a * cs - b * sn; q1[base + 1] = a * sn + b * cs;
    a = k1[base]; b = k1[base + 1];
    k1[base] = a * cs - b * sn; k1[base + 1] = a * sn + b * cs;
    a = q2[base]; b = q2[base + 1];
    q2[base] = a * cs - b * sn; q2[base + 1] = a * sn + b * cs;
    a = k2[base]; b = k2[base + 1];
    k2[base] = a * cs - b * sn; k2[base + 1] = a * sn + b * cs;
}

// ---------------- V pack: Vcat[h][s][0:64]=v_r, [64:128]=v_i ----------------
__global__ void pack_v_kernel(const float* __restrict__ vr,
                              const float* __restrict__ vi,
                              float* __restrict__ Vc)
{
    int idx = blockIdx.x * 256 + threadIdx.x;     // H*S*128 threads
    int c  = idx & 127;
    int sh = idx >> 7;                            // h*S + s
    int s  = sh & (S - 1);
    int hh = sh >> 11;
    float v = (c < HD) ? vr[(size_t)s * DIM + hh * HD + c]
                       : vi[(size_t)s * DIM + hh * HD + (c - HD)];
    Vc[idx] = v;
}

// ---------------- entanglement mix + phase rotation + cat packing ----------------
__global__ void entangle_kernel(const float* __restrict__ qr, const float* __restrict__ qi,
                                const float* __restrict__ kr, const float* __restrict__ ki,
                                const float* __restrict__ ent, const float* __restrict__ phase,
                                float* __restrict__ Qc, float* __restrict__ KR,
                                float* __restrict__ KI)
{
    int s = blockIdx.x;
    __shared__ float sqr[DIM], sqi[DIM], skr[DIM], ski[DIM];
    __shared__ float sent[H * H];
    int tid = threadIdx.x;
    if (tid < H * H) sent[tid] = ent[tid];
    for (int i = tid; i < DIM; i += 256) {
        size_t o = (size_t)s * DIM + i;
        sqr[i] = qr[o]; sqi[i] = qi[o]; skr[i] = kr[o]; ski[i] = ki[o];
    }
    __syncthreads();
    for (int p = tid; p < DIM; p += 256) {
        int x = p >> 6, d = p & 63;
        float aqr = 0.f, aqi = 0.f, akr = 0.f, aki = 0.f;
#pragma unroll
        for (int h2 = 0; h2 < H; h2++) {
            float e = sent[h2 * H + x];
            int o = h2 * HD + d;
            aqr = fmaf(sqr[o], e, aqr);
            aqi = fmaf(sqi[o], e, aqi);
            akr = fmaf(skr[o], e, akr);
            aki = fmaf(ski[o], e, aki);
        }
        float pv = phase[p];
        float ps, pc;
        sincosf(pv, &ps, &pc);
        float qr2 = aqr * pc - aqi * ps;
        float qi2 = aqr * ps + aqi * pc;
        float kr2 = akr * pc - aki * ps;
        float ki2 = akr * ps + aki * pc;
        size_t base = ((size_t)x * S + s) * 128;
        Qc[base + d]      = qr2;  Qc[base + HD + d] = qi2;
        KR[base + d]      = kr2;  KR[base + HD + d] = -ki2;
        KI[base + d]      = ki2;  KI[base + HD + d] = kr2;
    }
}

// ---------------- scores: mag epilogue, causal tiles only ----------------
__global__ __launch_bounds__(256, 2)
void scores_kernel(const float* __restrict__ Qc, const float* __restrict__ KRc,
                   const float* __restrict__ KIc,
                   const float* __restrict__ sc_is, const float* __restrict__ sc_at,
                   const float* __restrict__ sc_ce, float* __restrict__ mag)
{
    int h   = blockIdx.y;
    int lin = blockIdx.x;                        // 0..527, lower-tri tile index
    int ti  = (int)((sqrtf(8.f * lin + 1.f) - 1.f) * 0.5f);
    while ((ti + 1) * (ti + 2) / 2 <= lin) ++ti;
    while (ti * (ti + 1) / 2 > lin) --ti;
    int tj  = lin - ti * (ti + 1) / 2;
    int m0 = ti * 64, n0 = tj * 64;

    __shared__ float Qs[32][68];
    __shared__ float Rs[32][68];
    __shared__ float Is[32][68];

    int tid = threadIdx.x;
    int tm = (tid >> 4) * 4, tn = (tid & 15) * 4;
    float accr[4][4], acci[4][4];
#pragma unroll
    for (int i = 0; i < 4; i++)
#pragma unroll
        for (int j = 0; j < 4; j++) { accr[i][j] = 0.f; acci[i][j] = 0.f; }

    const float* qb = Qc  + ((size_t)h * S + m0) * 128;
    const float* rb = KRc + ((size_t)h * S + n0) * 128;
    const float* ib = KIc + ((size_t)h * S + n0) * 128;

    for (int k0 = 0; k0 < 128; k0 += 32) {
#pragma unroll
        for (int i = 0; i < 2; i++) {
            int idx = tid + i * 256;     // 0..511
            int row = idx >> 3;          // 0..63
            int kv  = (idx & 7) * 4;     // 0..28
            float4 q4 = *(const float4*)(qb + (size_t)row * 128 + k0 + kv);
            Qs[kv + 0][row] = q4.x; Qs[kv + 1][row] = q4.y;
            Qs[kv + 2][row] = q4.z; Qs[kv + 3][row] = q4.w;
            float4 r4 = *(const float4*)(rb + (size_t)row * 128 + k0 + kv);
            Rs[kv + 0][row] = r4.x; Rs[kv + 1][row] = r4.y;
            Rs[kv + 2][row] = r4.z; Rs[kv + 3][row] = r4.w;
            float4 i4 = *(const float4*)(ib + (size_t)row * 128 + k0 + kv);
            Is[kv + 0][row] = i4.x; Is[kv + 1][row] = i4.y;
            Is[kv + 2][row] = i4.z; Is[kv + 3][row] = i4.w;
        }
        __syncthreads();
#pragma unroll
        for (int kk = 0; kk < 32; kk++) {
            float a[4], br[4], bi[4];
            *(float4*)a  = *(const float4*)&Qs[kk][tm];
            *(float4*)br = *(const float4*)&Rs[kk][tn];
            *(float4*)bi = *(const float4*)&Is[kk][tn];
#pragma unroll
            for (int i = 0; i < 4; i++)
#pragma unroll
                for (int j = 0; j < 4; j++) {
                    accr[i][j] = fmaf(a[i], br[j], accr[i][j]);
                    acci[i][j] = fmaf(a[i], bi[j], acci[i][j]);
                }
        }
        __syncthreads();
    }

    float strength = 1.0f / (1.0f + expf(-*sc_is));
    float temp     = fmaxf(expf(*sc_at), 0.1f);
    float eps      = 0.03f / (1.0f + expf(-*sc_ce));
    float factor   = strength / temp;
    const float scale = 0.125f;   // 1/sqrt(64)

    float* out = mag + (size_t)h * S * S;
#pragma unroll
    for (int i = 0; i < 4; i++) {
        int s = m0 + tm + i;
#pragma unroll
        for (int j = 0; j < 4; j++) {
            int t = n0 + tn + j;
            float r  = accr[i][j] * scale;
            float im = acci[i][j] * scale;
            float ar = r + eps * im;
            float ai = im - eps * r;
            float m  = sqrtf(ar * ar + ai * ai + 1e-6f);
            out[(size_t)s * S + t] = (t <= s) ? m * factor : neg_inf();
        }
    }
}

// ---------------- row softmax (single-read, register resident) ----------------
__global__ void softmax_kernel(float* __restrict__ p)
{
    __shared__ float sm[8];
    int row = blockIdx.x;                  // h*S + s
    int s   = row & (S - 1);
    int L   = ((s >> 6) + 1) << 6;         // process to 64-tile end (masked entries are -inf)
    float* ptr = p + (size_t)row * S;
    int tid = threadIdx.x;

    float vals[8];
    float mx = neg_inf();
    int n = 0;
    for (int i = tid; i < L; i += 256) {
        float v = ptr[i];
        vals[n++] = v;
        mx = fmaxf(mx, v);
    }
#pragma unroll
    for (int o = 16; o > 0; o >>= 1) mx = fmaxf(mx, __shfl_xor_sync(0xffffffffu, mx, o));
    if ((tid & 31) == 0) sm[tid >> 5] = mx;
    __syncthreads();
    float tmx = sm[0];
#pragma unroll
    for (int i = 1; i < 8; i++) tmx = fmaxf(tmx, sm[i]);
    __syncthreads();

    float sum = 0.f;
    for (int k = 0; k < n; k++) {
        vals[k] = expf(vals[k] - tmx);     // expf(-inf)=0 handles the mask
        sum += vals[k];
    }
#pragma unroll
    for (int o = 16; o > 0; o >>= 1) sum += __shfl_xor_sync(0xffffffffu, sum, o);
    if ((tid & 31) == 0) sm[tid >> 5] = sum;
    __syncthreads();
    float tsum = 0.f;
#pragma unroll
    for (int i = 0; i < 8; i++) tsum += sm[i];

    float inv = 1.0f / tsum;
    n = 0;
    for (int i = tid; i < L; i += 256) ptr[i] = vals[n++] * inv;
}

// ---------------- P·Vcat (causal K range) ----------------
__global__ __launch_bounds__(256, 2)
void pv_kernel(const float* __restrict__ p, const float* __restrict__ Vc,
               float* __restrict__ outc)
{
    int h  = blockIdx.y;
    int ti = blockIdx.x;
    int m0 = ti * 64;

    __shared__ float Ps[32][68];
    __shared__ float Vs[32][132];

    int tid = threadIdx.x;
    int tm = (tid >> 4) * 4;        // 4 rows
    int tn = (tid & 15) * 8;        // 8 cols of 128
    float acc[4][8];
#pragma unroll
    for (int i = 0; i < 4; i++)
#pragma unroll
        for (int j = 0; j < 8; j++) acc[i][j] = 0.f;

    const float* prow  = p  + ((size_t)h * S + m0) * S;
    const float* vbase = Vc + (size_t)h * S * 128;
    int kend = (ti + 1) * 64;

    for (int t0 = 0; t0 < kend; t0 += 32) {
#pragma unroll
        for (int i = 0; i < 2; i++) {
            int idx = tid + i * 256;
            int row = idx >> 3;          // 0..63
            int kv  = (idx & 7) * 4;
            float4 p4 = *(const float4*)(prow + (size_t)row * S + t0 + kv);
            Ps[kv + 0][row] = p4.x; Ps[kv + 1][row] = p4.y;
            Ps[kv + 2][row] = p4.z; Ps[kv + 3][row] = p4.w;
        }
#pragma unroll
        for (int i = 0; i < 4; i++) {
            int idx = tid + i * 256;     // 0..1023
            int row = idx >> 5;          // 0..31
            int cv  = (idx & 31) * 4;
            float4 v4 = *(const float4*)(vbase + (size_t)(t0 + row) * 128 + cv);
            *(float4*)&Vs[row][cv] = v4;
        }
        __syncthreads();
#pragma unroll
        for (int kk = 0; kk < 32; kk++) {
            float a[4], b[8];
            *(float4*)a = *(const float4*)&Ps[kk][tm];
            *(float4*)&b[0] = *(const float4*)&Vs[kk][tn];
            *(float4*)&b[4] = *(const float4*)&Vs[kk][tn + 4];
#pragma unroll
            for (int i = 0; i < 4; i++)
#pragma unroll
                for (int j = 0; j < 8; j++)
                    acc[i][j] = fmaf(a[i], b[j], acc[i][j]);
        }
        __syncthreads();
    }

    // write: col<64 -> out_r plane, col>=64 -> out_i plane (tn is a multiple of 8)
    float* dst = (tn < HD) ? outc : outc + (size_t)S * DIM;
    int d0 = tn & 63;
#pragma unroll
    for (int i = 0; i < 4; i++) {
        int s = m0 + tm + i;
        float* crow = dst + (size_t)s * DIM + h * HD + d0;
        *(float4*)&crow[0] = *(float4*)&acc[i][0];
        *(float4*)&crow[4] = *(float4*)&acc[i][4];
    }
}

// ---------------- host ----------------
extern "C" void kernel_launch(void* const* d_in, const int* in_sizes, int n_in,
                              void* d_out, int out_size)
{
    const float* real  = (const float*)d_in[0];
    const float* imag  = (const float*)d_in[1];
    const float* Wq_r  = (const float*)d_in[2];
    const float* bq_r  = (const float*)d_in[3];
    const float* Wk_r  = (const float*)d_in[4];
    const float* bk_r  = (const float*)d_in[5];
    const float* Wv_r  = (const float*)d_in[6];
    const float* bv_r  = (const float*)d_in[7];
    const float* Wq_i  = (const float*)d_in[8];
    const float* bq_i  = (const float*)d_in[9];
    const float* Wk_i  = (const float*)d_in[10];
    const float* bk_i  = (const float*)d_in[11];
    const float* Wv_i  = (const float*)d_in[12];
    const float* bv_i  = (const float*)d_in[13];
    const float* Wo_r  = (const float*)d_in[14];
    const float* bo_r  = (const float*)d_in[15];
    const float* Wo_i  = (const float*)d_in[16];
    const float* bo_i  = (const float*)d_in[17];
    const float* phase = (const float*)d_in[18];
    const float* ent   = (const float*)d_in[19];
    const float* rfreq = (const float*)d_in[20];
    const float* s_is  = (const float*)d_in[21];
    const float* s_at  = (const float*)d_in[22];
    const float* s_ce  = (const float*)d_in[23];

    float *qr, *kr, *vr, *qi, *ki, *vi, *Qc, *KR, *KI, *Vc, *scores, *attn;
    cudaGetSymbolAddress((void**)&qr, g_qr);
    cudaGetSymbolAddress((void**)&kr, g_kr);
    cudaGetSymbolAddress((void**)&vr, g_vr);
    cudaGetSymbolAddress((void**)&qi, g_qi);
    cudaGetSymbolAddress((void**)&ki, g_ki);
    cudaGetSymbolAddress((void**)&vi, g_vi);
    cudaGetSymbolAddress((void**)&Qc, g_Qc);
    cudaGetSymbolAddress((void**)&KR, g_KR);
    cudaGetSymbolAddress((void**)&KI, g_KI);
    cudaGetSymbolAddress((void**)&Vc, g_Vc);
    cudaGetSymbolAddress((void**)&scores, g_scores);
    cudaGetSymbolAddress((void**)&attn, g_attn);

    __nv_bfloat16 *rhi, *rlo, *ihi, *ilo, *whi, *wlo, *wohi, *wolo, *ahi, *alo;
    cudaGetSymbolAddress((void**)&rhi,  g_real_hi);
    cudaGetSymbolAddress((void**)&rlo,  g_real_lo);
    cudaGetSymbolAddress((void**)&ihi,  g_imag_hi);
    cudaGetSymbolAddress((void**)&ilo,  g_imag_lo);
    cudaGetSymbolAddress((void**)&whi,  g_W_hi);
    cudaGetSymbolAddress((void**)&wlo,  g_W_lo);
    cudaGetSymbolAddress((void**)&wohi, g_Wo_hi);
    cudaGetSymbolAddress((void**)&wolo, g_Wo_lo);
    cudaGetSymbolAddress((void**)&ahi,  g_attn_hi);
    cudaGetSymbolAddress((void**)&alo,  g_attn_lo);

    float* out = (float*)d_out;

    cudaFuncSetAttribute(mm_bf16x3_kernel,
                         cudaFuncAttributeMaxDynamicSharedMemorySize, 2 * MM_STAGE);

    const int SD4 = S * DIM / 4;      // float4 count for a [S,DIM] tensor
    const int DD4 = DIM * DIM / 4;

    // 0) split activations + weights to bf16 hi/lo
    split_kernel<<<(SD4 + 255) / 256, 256>>>(real, rhi, rlo, SD4);
    split_kernel<<<(SD4 + 255) / 256, 256>>>(imag, ihi, ilo, SD4);
    const float* Ws[6] = {Wq_r, Wk_r, Wv_r, Wq_i, Wk_i, Wv_i};
    for (int w = 0; w < 6; w++)
        split_kernel<<<(DD4 + 255) / 256, 256>>>(Ws[w], whi + (size_t)w * DIM * DIM,
                                                 wlo + (size_t)w * DIM * DIM, DD4);
    split_kernel<<<(DD4 + 255) / 256, 256>>>(Wo_r, wohi, wolo, DD4);
    split_kernel<<<(DD4 + 255) / 256, 256>>>(Wo_i, wohi + (size_t)DIM * DIM,
                                             wolo + (size_t)DIM * DIM, DD4);

    // 1) six input projections (mma.sync bf16x3)
    MMArgs gp = {};
    float* outs6[6]      = {qr, kr, vr, qi, ki, vi};
    const float* bs6[6]  = {bq_r, bk_r, bv_r, bq_i, bk_i, bv_i};
    for (int w = 0; w < 6; w++) {
        gp.Ahi[w] = (w < 3) ? rhi : ihi;
        gp.Alo[w] = (w < 3) ? rlo : ilo;
        gp.Bhi[w] = whi + (size_t)w * DIM * DIM;
        gp.Blo[w] = wlo + (size_t)w * DIM * DIM;
        gp.bias[w] = bs6[w];
        gp.C[w]   = outs6[w];
    }
    mm_bf16x3_kernel<<<dim3(DIM / 128, S / 128, 6), 256, 2 * MM_STAGE>>>(gp, S, DIM, DIM);

    // 2) RoPE on q_r, k_r, q_i, k_i
    rope_kernel<<<(S * H * 16) / 256, 256>>>(qr, kr, qi, ki, rfreq);

    // 3) pack V
    pack_v_kernel<<<(H * S * 128) / 256, 256>>>(vr, vi, Vc);

    // 4) entanglement + phase, emit Qcat/KRcat/KIcat
    entangle_kernel<<<S, 256>>>(qr, qi, kr, ki, ent, phase, Qc, KR, KI);

    // 5) causal score magnitudes (528 lower-tri 64x64 tiles per head)
    scores_kernel<<<dim3(528, H), 256>>>(Qc, KR, KI, s_is, s_at, s_ce, scores);

    // 6) softmax per row
    softmax_kernel<<<H * S, 256>>>(scores);

    // 7) attention output (both r and i via Vcat)
    pv_kernel<<<dim3(S / 64, H), 256>>>(scores, Vc, attn);

    // 8) two output projections (mma.sync bf16x3)
    split_kernel<<<(2 * SD4 + 255) / 256, 256>>>(attn, ahi, alo, 2 * SD4);
    MMArgs go = {};
    go.Ahi[0] = ahi;              go.Alo[0] = alo;
    go.Bhi[0] = wohi;             go.Blo[0] = wolo;
    go.bias[0] = bo_r;            go.C[0] = out;
    go.Ahi[1] = ahi + (size_t)S * DIM;  go.Alo[1] = alo + (size_t)S * DIM;
    go.Bhi[1] = wohi + (size_t)DIM * DIM; go.Blo[1] = wolo + (size_t)DIM * DIM;
    go.bias[1] = bo_i;            go.C[1] = out + (size_t)S * DIM;
    mm_bf16x3_kernel<<<dim3(DIM / 128, S / 128, 2), 256, 2 * MM_STAGE>>>(go, S, DIM, DIM);
}

// round 5
// speedup vs baseline: 2.6967x; 2.0291x over previous
#include <cuda_runtime.h>
#include <cuda_bf16.h>
#include <math.h>
#include <stdint.h>

#define S   2048
#define DIM 1024
#define H   16
#define HD  64

// ---------------- scratch (__device__ globals: allocation-free) ----------------
__device__ float g_qr[S*DIM];
__device__ float g_kr[S*DIM];
__device__ float g_vr[S*DIM];
__device__ float g_qi[S*DIM];
__device__ float g_ki[S*DIM];
__device__ float g_vi[S*DIM];
__device__ float g_scores[(size_t)H*S*S];   // fp32 magnitudes, 256 MB
__device__ float g_attn[2*S*DIM];           // attention outputs (r then i)

// bf16 split planes (projection GEMMs)
__device__ __nv_bfloat16 g_real_hi[S*DIM],  g_real_lo[S*DIM];
__device__ __nv_bfloat16 g_imag_hi[S*DIM],  g_imag_lo[S*DIM];
__device__ __nv_bfloat16 g_W_hi[6*DIM*DIM], g_W_lo[6*DIM*DIM];
__device__ __nv_bfloat16 g_Wo_hi[2*DIM*DIM], g_Wo_lo[2*DIM*DIM];
__device__ __nv_bfloat16 g_attn_hi[2*S*DIM], g_attn_lo[2*S*DIM];

// bf16 attention operand planes
__device__ __nv_bfloat16 g_qhi[H*S*128],  g_qlo[H*S*128];   // [h][s][qr|qi]
__device__ __nv_bfloat16 g_krhi[H*S*128], g_krlo[H*S*128];  // [h][s][kr|-ki]
__device__ __nv_bfloat16 g_kihi[H*S*128], g_kilo[H*S*128];  // [h][s][ki| kr]
__device__ __nv_bfloat16 g_vthi[H*128*S], g_vtlo[H*128*S];  // [h][n][t] (V transposed)
__device__ __nv_bfloat16 g_phi[(size_t)H*S*S], g_plo[(size_t)H*S*S];  // softmax P

__device__ __forceinline__ float neg_inf() { return __int_as_float(0xff800000); }

__device__ __forceinline__ uint32_t smem_to_u32(const void* smem_ptr) {
    uint32_t addr;
    asm("{ .reg .u64 tmp; cvta.to.shared.u64 tmp, %1; cvt.u32.u64 %0, tmp; }"
        : "=r"(addr) : "l"(smem_ptr));
    return addr;
}
__device__ __forceinline__ void ldm_x4(uint32_t* r, uint32_t addr) {
    asm volatile("ldmatrix.sync.aligned.m8n8.x4.shared.b16 {%0,%1,%2,%3}, [%4];"
        : "=r"(r[0]), "=r"(r[1]), "=r"(r[2]), "=r"(r[3]) : "r"(addr));
}
__device__ __forceinline__ void mma_bf16(float* c, const uint32_t* a,
                                         uint32_t b0, uint32_t b1) {
    asm volatile("mma.sync.aligned.m16n8k16.row.col.f32.bf16.bf16.f32 "
        "{%0,%1,%2,%3}, {%4,%5,%6,%7}, {%8,%9}, {%0,%1,%2,%3};"
        : "+f"(c[0]), "+f"(c[1]), "+f"(c[2]), "+f"(c[3])
        : "r"(a[0]), "r"(a[1]), "r"(a[2]), "r"(a[3]), "r"(b0), "r"(b1));
}
__device__ __forceinline__ void cp16(uint32_t dst, const void* src) {
    asm volatile("cp.async.cg.shared.global [%0], [%1], 16;" :: "r"(dst), "l"(src));
}
__device__ __forceinline__ void cp_commit() {
    asm volatile("cp.async.commit_group;" ::: "memory");
}
template<int N> __device__ __forceinline__ void cp_wait() {
    asm volatile("cp.async.wait_group %0;" :: "n"(N) : "memory");
}

// swizzle within a plane of 128B rows (8 chunks of 16B per row)
__device__ __forceinline__ uint32_t swz(int r, int c) {
    return (uint32_t)(r * 128 + ((c ^ (r & 7)) << 4));
}

__device__ __forceinline__ void split_store(__nv_bfloat16* hi, __nv_bfloat16* lo,
                                            size_t o, float v) {
    __nv_bfloat16 h = __float2bfloat16(v);
    hi[o] = h;
    lo[o] = __float2bfloat16(v - __bfloat162float(h));
}

// ---------------- fp32 -> (hi, lo) bf16 split ----------------
__global__ void split_kernel(const float* __restrict__ x,
                             __nv_bfloat16* __restrict__ hi,
                             __nv_bfloat16* __restrict__ lo, int n4)
{
    int i = blockIdx.x * 256 + threadIdx.x;
    if (i >= n4) return;
    float4 v = ((const float4*)x)[i];
    __nv_bfloat16 h0 = __float2bfloat16(v.x);
    __nv_bfloat16 h1 = __float2bfloat16(v.y);
    __nv_bfloat16 h2 = __float2bfloat16(v.z);
    __nv_bfloat16 h3 = __float2bfloat16(v.w);
    __nv_bfloat162 hA; hA.x = h0; hA.y = h1;
    __nv_bfloat162 hB; hB.x = h2; hB.y = h3;
    ((__nv_bfloat162*)hi)[2*i]   = hA;
    ((__nv_bfloat162*)hi)[2*i+1] = hB;
    __nv_bfloat162 lA, lB;
    lA.x = __float2bfloat16(v.x - __bfloat162float(h0));
    lA.y = __float2bfloat16(v.y - __bfloat162float(h1));
    lB.x = __float2bfloat16(v.z - __bfloat162float(h2));
    lB.y = __float2bfloat16(v.w - __bfloat162float(h3));
    ((__nv_bfloat162*)lo)[2*i]   = lA;
    ((__nv_bfloat162*)lo)[2*i+1] = lB;
}

// ---------------- batched mma.sync GEMM: C = A·Bᵀ + bias (bf16x3) ----------------
struct MMArgs {
    const __nv_bfloat16* Ahi[8];
    const __nv_bfloat16* Alo[8];
    const __nv_bfloat16* Bhi[8];
    const __nv_bfloat16* Blo[8];
    const float*         bias[8];
    float*               C[8];
};

#define MM_STAGE 65536u

__global__ __launch_bounds__(256, 1)
void mm_bf16x3_kernel(MMArgs ga, int M, int N, int K)
{
    extern __shared__ __align__(1024) char smem[];
    const int z = blockIdx.z;
    const __nv_bfloat16* __restrict__ Ahi = ga.Ahi[z];
    const __nv_bfloat16* __restrict__ Alo = ga.Alo[z];
    const __nv_bfloat16* __restrict__ Bhi = ga.Bhi[z];
    const __nv_bfloat16* __restrict__ Blo = ga.Blo[z];
    const float* __restrict__ bias = ga.bias[z];
    float* __restrict__       C    = ga.C[z];

    const int m0 = blockIdx.y * 128;
    const int n0 = blockIdx.x * 128;

    const int tid  = threadIdx.x;
    const int lane = tid & 31;
    const int wid  = tid >> 5;
    const int wm   = (wid & 1) * 64;
    const int wn   = (wid >> 1) * 32;

    uint32_t sb = smem_to_u32(smem);

    float acc[4][4][4];
#pragma unroll
    for (int a = 0; a < 4; a++)
#pragma unroll
        for (int b = 0; b < 4; b++)
#pragma unroll
            for (int c = 0; c < 4; c++) acc[a][b][c] = 0.f;

    const int NIT = K / 64;

    auto fill = [&](int it, int buf) {
        int k0 = it * 64;
        uint32_t so = sb + buf * MM_STAGE;
#pragma unroll
        for (int i = 0; i < 4; i++) {
            int q = tid + i * 256;
            int r = q >> 3, c = q & 7;
            uint32_t off = swz(r, c);
            cp16(so +          off, Ahi + (size_t)(m0 + r) * K + k0 + c * 8);
            cp16(so + 16384u + off, Alo + (size_t)(m0 + r) * K + k0 + c * 8);
            cp16(so + 32768u + off, Bhi + (size_t)(n0 + r) * K + k0 + c * 8);
            cp16(so + 49152u + off, Blo + (size_t)(n0 + r) * K + k0 + c * 8);
        }
    };

    fill(0, 0);
    cp_commit();

    for (int it = 0; it < NIT; it++) {
        if (it + 1 < NIT) { fill(it + 1, (it + 1) & 1); cp_commit(); cp_wait<1>(); }
        else              { cp_wait<0>(); }
        __syncthreads();

        uint32_t so = sb + (uint32_t)(it & 1) * MM_STAGE;
#pragma unroll
        for (int kk = 0; kk < 64; kk += 16) {
            int ck = kk >> 3;
            uint32_t ah[4][4], al[4][4];
#pragma unroll
            for (int mt = 0; mt < 4; mt++) {
                int r = wm + mt * 16 + (lane & 15);
                int c = ck + (lane >> 4);
                uint32_t off = swz(r, c);
                ldm_x4(ah[mt], so + off);
                ldm_x4(al[mt], so + 16384u + off);
            }
            uint32_t bh[2][4], bl[2][4];
#pragma unroll
            for (int p = 0; p < 2; p++) {
                int r = wn + p * 16 + (lane & 7) + ((lane >> 4) << 3);
                int c = ck + ((lane >> 3) & 1);
                uint32_t off = swz(r, c);
                ldm_x4(bh[p], so + 32768u + off);
                ldm_x4(bl[p], so + 49152u + off);
            }
#pragma unroll
            for (int mt = 0; mt < 4; mt++)
#pragma unroll
                for (int nt = 0; nt < 4; nt++) {
                    uint32_t b0h = bh[nt >> 1][(nt & 1) * 2];
                    uint32_t b1h = bh[nt >> 1][(nt & 1) * 2 + 1];
                    uint32_t b0l = bl[nt >> 1][(nt & 1) * 2];
                    uint32_t b1l = bl[nt >> 1][(nt & 1) * 2 + 1];
                    mma_bf16(acc[mt][nt], ah[mt], b0h, b1h);
                    mma_bf16(acc[mt][nt], ah[mt], b0l, b1l);
                    mma_bf16(acc[mt][nt], al[mt], b0h, b1h);
                }
        }
        __syncthreads();
    }

#pragma unroll
    for (int mt = 0; mt < 4; mt++) {
        int m = m0 + wm + mt * 16 + (lane >> 2);
#pragma unroll
        for (int nt = 0; nt < 4; nt++) {
            int n = n0 + wn + nt * 8 + (lane & 3) * 2;
            float2 bv = *(const float2*)(bias + n);
            float2 o0, o1;
            o0.x = acc[mt][nt][0] + bv.x;
            o0.y = acc[mt][nt][1] + bv.y;
            o1.x = acc[mt][nt][2] + bv.x;
            o1.y = acc[mt][nt][3] + bv.y;
            *(float2*)(C + (size_t)m * N + n)       = o0;
            *(float2*)(C + (size_t)(m + 8) * N + n) = o1;
        }
    }
}

// ---------------- RoPE (in place on q_r,k_r,q_i,k_i) ----------------
__global__ void rope_kernel(float* q1, float* k1, float* q2, float* k2,
                            const float* __restrict__ freqs)
{
    int idx = blockIdx.x * 256 + threadIdx.x;
    int j  = idx & 15;
    int hh = (idx >> 4) & 15;
    int s  = idx >> 8;
    float ang = (float)s * freqs[j];
    float sn, cs;
    sincosf(ang, &sn, &cs);
    size_t base = (size_t)s * DIM + hh * HD + 2 * j;
    float a, b;
    a = q1[base]; b = q1[base + 1];
    q1[base] = a * cs - b * sn; q1[base + 1] = a * sn + b * cs;
    a = k1[base]; b = k1[base + 1];
    k1[base] = a * cs - b * sn; k1[base + 1] = a * sn + b * cs;
    a = q2[base]; b = q2[base + 1];
    q2[base] = a * cs - b * sn; q2[base + 1] = a * sn + b * cs;
    a = k2[base]; b = k2[base + 1];
    k2[base] = a * cs - b * sn; k2[base + 1] = a * sn + b * cs;
}

// ---------------- V transpose + bf16 split: Vt[h][n=128][t] ----------------
__global__ void pack_vt_kernel(const float* __restrict__ vr,
                               const float* __restrict__ vi,
                               __nv_bfloat16* __restrict__ Vthi,
                               __nv_bfloat16* __restrict__ Vtlo)
{
    int h  = blockIdx.y;
    int t0 = blockIdx.x * 64;
    __shared__ float tr[64][65], tim[64][65];
    int tid = threadIdx.x;
#pragma unroll
    for (int i = 0; i < 16; i++) {
        int q = tid + i * 256;          // 0..4095
        int t = q >> 6, c = q & 63;
        tr[t][c]  = vr[(size_t)(t0 + t) * DIM + h * HD + c];
        tim[t][c] = vi[(size_t)(t0 + t) * DIM + h * HD + c];
    }
    __syncthreads();
#pragma unroll
    for (int i = 0; i < 32; i++) {
        int q = tid + i * 256;          // 0..8191
        int c = q >> 6, t = q & 63;
        float v = (c < 64) ? tr[t][c] : tim[t][c - 64];
        size_t o = ((size_t)(h * 128 + c)) * S + t0 + t;
        split_store(Vthi, Vtlo, o, v);
    }
}

// ---------------- entanglement + phase -> bf16 hi/lo attention operands ----------------
__global__ void entangle_kernel(const float* __restrict__ qr, const float* __restrict__ qi,
                                const float* __restrict__ kr, const float* __restrict__ ki,
                                const float* __restrict__ ent, const float* __restrict__ phase,
                                __nv_bfloat16* __restrict__ Qhi, __nv_bfloat16* __restrict__ Qlo,
                                __nv_bfloat16* __restrict__ Rhi, __nv_bfloat16* __restrict__ Rlo,
                                __nv_bfloat16* __restrict__ Ihi, __nv_bfloat16* __restrict__ Ilo)
{
    int s = blockIdx.x;
    __shared__ float sqr[DIM], sqi[DIM], skr[DIM], ski[DIM];
    __shared__ float sent[H * H];
    int tid = threadIdx.x;
    if (tid < H * H) sent[tid] = ent[tid];
    for (int i = tid; i < DIM; i += 256) {
        size_t o = (size_t)s * DIM + i;
        sqr[i] = qr[o]; sqi[i] = qi[o]; skr[i] = kr[o]; ski[i] = ki[o];
    }
    __syncthreads();
    for (int p = tid; p < DIM; p += 256) {
        int x = p >> 6, d = p & 63;
        float aqr = 0.f, aqi = 0.f, akr = 0.f, aki = 0.f;
#pragma unroll
        for (int h2 = 0; h2 < H; h2++) {
            float e = sent[h2 * H + x];
            int o = h2 * HD + d;
            aqr = fmaf(sqr[o], e, aqr);
            aqi = fmaf(sqi[o], e, aqi);
            akr = fmaf(skr[o], e, akr);
            aki = fmaf(ski[o], e, aki);
        }
        float pv = phase[p];
        float ps, pc;
        sincosf(pv, &ps, &pc);
        float qr2 = aqr * pc - aqi * ps;
        float qi2 = aqr * ps + aqi * pc;
        float kr2 = akr * pc - aki * ps;
        float ki2 = akr * ps + aki * pc;
        size_t base = ((size_t)x * S + s) * 128;
        split_store(Qhi, Qlo, base + d,      qr2);
        split_store(Qhi, Qlo, base + HD + d, qi2);
        split_store(Rhi, Rlo, base + d,      kr2);
        split_store(Rhi, Rlo, base + HD + d, -ki2);
        split_store(Ihi, Ilo, base + d,      ki2);
        split_store(Ihi, Ilo, base + HD + d, kr2);
    }
}

// ---------------- scores via mma (bf16x3), magnitude epilogue ----------------
// planes in smem: Qhi 0, Qlo 16K, Rhi 32K, Rlo 48K, Ihi 64K, Ilo 80K (96KB)
// each plane: [64 rows][128 cols] bf16 stored as two 8KB sub-planes of 64 cols
__global__ __launch_bounds__(256, 2)
void scores_mma_kernel(const __nv_bfloat16* __restrict__ Qhi, const __nv_bfloat16* __restrict__ Qlo,
                       const __nv_bfloat16* __restrict__ Rhi, const __nv_bfloat16* __restrict__ Rlo,
                       const __nv_bfloat16* __restrict__ Ihi, const __nv_bfloat16* __restrict__ Ilo,
                       const float* __restrict__ sc_is, const float* __restrict__ sc_at,
                       const float* __restrict__ sc_ce, float* __restrict__ mag)
{
    extern __shared__ __align__(1024) char smem[];
    int h   = blockIdx.y;
    int lin = blockIdx.x;
    int ti  = (int)((sqrtf(8.f * lin + 1.f) - 1.f) * 0.5f);
    while ((ti + 1) * (ti + 2) / 2 <= lin) ++ti;
    while (ti * (ti + 1) / 2 > lin) --ti;
    int tj  = lin - ti * (ti + 1) / 2;
    int m0 = ti * 64, n0 = tj * 64;

    uint32_t sb = smem_to_u32(smem);
    int tid = threadIdx.x, lane = tid & 31, wid = tid >> 5;
    int wm = (wid & 3) * 16, wn = (wid >> 2) * 32;

    const __nv_bfloat16* srcs[6] = {Qhi, Qlo, Rhi, Rlo, Ihi, Ilo};
    const int rows0[6] = {m0, m0, n0, n0, n0, n0};
#pragma unroll
    for (int pl = 0; pl < 6; pl++) {
        const __nv_bfloat16* sp = srcs[pl] + ((size_t)h * S + rows0[pl]) * 128;
        uint32_t pb = sb + pl * 16384u;
#pragma unroll
        for (int i = 0; i < 4; i++) {
            int q = tid + i * 256;          // 0..1023
            int r = q >> 4, cg = q & 15;
            uint32_t dst = pb + ((cg & 8) ? 8192u : 0u) + swz(r, cg & 7);
            cp16(dst, sp + (size_t)r * 128 + cg * 8);
        }
    }
    cp_commit(); cp_wait<0>();
    __syncthreads();

    float accr[4][4], acci[4][4];
#pragma unroll
    for (int a = 0; a < 4; a++)
#pragma unroll
        for (int c = 0; c < 4; c++) { accr[a][c] = 0.f; acci[a][c] = 0.f; }

#pragma unroll
    for (int ck = 0; ck < 16; ck += 2) {
        uint32_t ah[4], al[4];
        {
            int r = wm + (lane & 15);
            int cg = ck + (lane >> 4);
            uint32_t off = ((cg & 8) ? 8192u : 0u) + swz(r, cg & 7);
            ldm_x4(ah, sb + off);
            ldm_x4(al, sb + 16384u + off);
        }
#pragma unroll
        for (int p = 0; p < 2; p++) {
            int r = wn + p * 16 + (lane & 7) + ((lane >> 4) << 3);
            int cg = ck + ((lane >> 3) & 1);
            uint32_t off = ((cg & 8) ? 8192u : 0u) + swz(r, cg & 7);
            uint32_t rh[4], rl[4], ih[4], il[4];
            ldm_x4(rh, sb + 32768u + off);
            ldm_x4(rl, sb + 49152u + off);
            ldm_x4(ih, sb + 65536u + off);
            ldm_x4(il, sb + 81920u + off);
#pragma unroll
            for (int e2 = 0; e2 < 2; e2++) {
                int nt = p * 2 + e2, e = e2 * 2;
                mma_bf16(accr[nt], ah, rh[e], rh[e + 1]);
                mma_bf16(accr[nt], ah, rl[e], rl[e + 1]);
                mma_bf16(accr[nt], al, rh[e], rh[e + 1]);
                mma_bf16(acci[nt], ah, ih[e], ih[e + 1]);
                mma_bf16(acci[nt], ah, il[e], il[e + 1]);
                mma_bf16(acci[nt], al, ih[e], ih[e + 1]);
            }
        }
    }

    float strength = 1.0f / (1.0f + expf(-*sc_is));
    float temp     = fmaxf(expf(*sc_at), 0.1f);
    float eps      = 0.03f / (1.0f + expf(-*sc_ce));
    float factor   = strength / temp;
    const float scale = 0.125f;

    float* out = mag + (size_t)h * S * S;
#pragma unroll
    for (int nt = 0; nt < 4; nt++) {
        int col = n0 + wn + nt * 8 + (lane & 3) * 2;
#pragma unroll
        for (int half = 0; half < 2; half++) {
            int row = m0 + wm + (lane >> 2) + half * 8;
#pragma unroll
            for (int e = 0; e < 2; e++) {
                float r  = accr[nt][half * 2 + e] * scale;
                float im = acci[nt][half * 2 + e] * scale;
                float ar = r + eps * im;
                float ai = im - eps * r;
                float m  = sqrtf(ar * ar + ai * ai + 1e-6f);
                int c = col + e;
                out[(size_t)row * S + c] = (c <= row) ? m * factor : neg_inf();
            }
        }
    }
}

// ---------------- row softmax -> bf16 hi/lo P planes ----------------
__global__ void softmax_kernel(const float* __restrict__ p,
                               __nv_bfloat16* __restrict__ phi,
                               __nv_bfloat16* __restrict__ plo)
{
    __shared__ float sm[8];
    int row = blockIdx.x;                  // h*S + s
    int s   = row & (S - 1);
    int L   = ((s >> 6) + 1) << 6;
    const float* ptr = p + (size_t)row * S;
    int tid = threadIdx.x;

    float vals[8];
    float mx = neg_inf();
    int n = 0;
    for (int i = tid; i < L; i += 256) {
        float v = ptr[i];
        vals[n++] = v;
        mx = fmaxf(mx, v);
    }
#pragma unroll
    for (int o = 16; o > 0; o >>= 1) mx = fmaxf(mx, __shfl_xor_sync(0xffffffffu, mx, o));
    if ((tid & 31) == 0) sm[tid >> 5] = mx;
    __syncthreads();
    float tmx = sm[0];
#pragma unroll
    for (int i = 1; i < 8; i++) tmx = fmaxf(tmx, sm[i]);
    __syncthreads();

    float sum = 0.f;
    for (int k = 0; k < n; k++) {
        vals[k] = expf(vals[k] - tmx);
        sum += vals[k];
    }
#pragma unroll
    for (int o = 16; o > 0; o >>= 1) sum += __shfl_xor_sync(0xffffffffu, sum, o);
    if ((tid & 31) == 0) sm[tid >> 5] = sum;
    __syncthreads();
    float tsum = 0.f;
#pragma unroll
    for (int i = 0; i < 8; i++) tsum += sm[i];

    float inv = 1.0f / tsum;
    n = 0;
    for (int i = tid; i < L; i += 256) {
        float v = vals[n++] * inv;
        split_store(phi, plo, (size_t)row * S + i, v);
    }
}

// ---------------- P·V via mma (bf16x3), causal K loop ----------------
// stage: Phi 0 (8K), Plo 8K, Vthi 16K (16K), Vtlo 32K; stride 48K; 2 stages
__global__ __launch_bounds__(256, 2)
void pv_mma_kernel(const __nv_bfloat16* __restrict__ Phi, const __nv_bfloat16* __restrict__ Plo,
                   const __nv_bfloat16* __restrict__ Vthi, const __nv_bfloat16* __restrict__ Vtlo,
                   float* __restrict__ outc)
{
    extern __shared__ __align__(1024) char smem[];
    int h  = blockIdx.y;
    int ti = blockIdx.x;
    int m0 = ti * 64;
    uint32_t sb = smem_to_u32(smem);
    int tid = threadIdx.x, lane = tid & 31, wid = tid >> 5;
    int wm = (wid & 3) * 16, wn = (wid >> 2) * 64;

    float acc[8][4];
#pragma unroll
    for (int a = 0; a < 8; a++)
#pragma unroll
        for (int c = 0; c < 4; c++) acc[a][c] = 0.f;

    const int nstg = ti + 1;

    auto fill = [&](int it, int buf) {
        int t0 = it * 64;
        uint32_t so = sb + (uint32_t)buf * 49152u;
#pragma unroll
        for (int i = 0; i < 4; i++) {
            int q = tid + i * 256;          // 0..1023
            int pl = q >> 9, r = (q >> 3) & 63, c = q & 7;
            const __nv_bfloat16* sp = (pl ? Plo : Phi)
                + ((size_t)(h * S + m0 + r)) * S + t0 + c * 8;
            cp16(so + pl * 8192u + swz(r, c), sp);
        }
#pragma unroll
        for (int i = 0; i < 8; i++) {
            int q = tid + i * 256;          // 0..2047
            int pl = q >> 10, r = (q >> 3) & 127, c = q & 7;
            const __nv_bfloat16* sp = (pl ? Vtlo : Vthi)
                + ((size_t)(h * 128 + r)) * S + t0 + c * 8;
            cp16(so + 16384u + pl * 16384u + swz(r, c), sp);
        }
    };

    fill(0, 0);
    cp_commit();

    for (int it = 0; it < nstg; it++) {
        if (it + 1 < nstg) { fill(it + 1, (it + 1) & 1); cp_commit(); cp_wait<1>(); }
        else               { cp_wait<0>(); }
        __syncthreads();

        uint32_t so = sb + (uint32_t)(it & 1) * 49152u;
#pragma unroll
        for (int ck = 0; ck < 8; ck += 2) {
            uint32_t ah[4], al[4];
            {
                int r = wm + (lane & 15);
                int cg = ck + (lane >> 4);
                uint32_t off = swz(r, cg);
                ldm_x4(ah, so + off);
                ldm_x4(al, so + 8192u + off);
            }
#pragma unroll
            for (int p = 0; p < 4; p++) {
                int r = wn + p * 16 + (lane & 7) + ((lane >> 4) << 3);
                int cg = ck + ((lane >> 3) & 1);
                uint32_t off = swz(r, cg);
                uint32_t bh[4], bl[4];
                ldm_x4(bh, so + 16384u + off);
                ldm_x4(bl, so + 32768u + off);
#pragma unroll
                for (int e2 = 0; e2 < 2; e2++) {
                    int nt = p * 2 + e2, e = e2 * 2;
                    mma_bf16(acc[nt], ah, bh[e], bh[e + 1]);
                    mma_bf16(acc[nt], ah, bl[e], bl[e + 1]);
                    mma_bf16(acc[nt], al, bh[e], bh[e + 1]);
                }
            }
        }
        __syncthreads();
    }

    // epilogue: col<64 -> out_r plane, col>=64 -> out_i plane
#pragma unroll
    for (int nt = 0; nt < 8; nt++) {
        int col = wn + nt * 8 + (lane & 3) * 2;
        float* dst = (col < HD) ? outc : outc + (size_t)S * DIM;
        int d0 = col & 63;
        int row = m0 + wm + (lane >> 2);
        float2 o0, o1;
        o0.x = acc[nt][0]; o0.y = acc[nt][1];
        o1.x = acc[nt][2]; o1.y = acc[nt][3];
        *(float2*)(dst + (size_t)row * DIM + h * HD + d0)       = o0;
        *(float2*)(dst + (size_t)(row + 8) * DIM + h * HD + d0) = o1;
    }
}

// ---------------- host ----------------
extern "C" void kernel_launch(void* const* d_in, const int* in_sizes, int n_in,
                              void* d_out, int out_size)
{
    const float* real  = (const float*)d_in[0];
    const float* imag  = (const float*)d_in[1];
    const float* Wq_r  = (const float*)d_in[2];
    const float* bq_r  = (const float*)d_in[3];
    const float* Wk_r  = (const float*)d_in[4];
    const float* bk_r  = (const float*)d_in[5];
    const float* Wv_r  = (const float*)d_in[6];
    const float* bv_r  = (const float*)d_in[7];
    const float* Wq_i  = (const float*)d_in[8];
    const float* bq_i  = (const float*)d_in[9];
    const float* Wk_i  = (const float*)d_in[10];
    const float* bk_i  = (const float*)d_in[11];
    const float* Wv_i  = (const float*)d_in[12];
    const float* bv_i  = (const float*)d_in[13];
    const float* Wo_r  = (const float*)d_in[14];
    const float* bo_r  = (const float*)d_in[15];
    const float* Wo_i  = (const float*)d_in[16];
    const float* bo_i  = (const float*)d_in[17];
    const float* phase = (const float*)d_in[18];
    const float* ent   = (const float*)d_in[19];
    const float* rfreq = (const float*)d_in[20];
    const float* s_is  = (const float*)d_in[21];
    const float* s_at  = (const float*)d_in[22];
    const float* s_ce  = (const float*)d_in[23];

    float *qr, *kr, *vr, *qi, *ki, *vi, *scores, *attn;
    cudaGetSymbolAddress((void**)&qr, g_qr);
    cudaGetSymbolAddress((void**)&kr, g_kr);
    cudaGetSymbolAddress((void**)&vr, g_vr);
    cudaGetSymbolAddress((void**)&qi, g_qi);
    cudaGetSymbolAddress((void**)&ki, g_ki);
    cudaGetSymbolAddress((void**)&vi, g_vi);
    cudaGetSymbolAddress((void**)&scores, g_scores);
    cudaGetSymbolAddress((void**)&attn, g_attn);

    __nv_bfloat16 *rhi, *rlo, *ihi, *ilo, *whi, *wlo, *wohi, *wolo, *ahi, *alo;
    cudaGetSymbolAddress((void**)&rhi,  g_real_hi);
    cudaGetSymbolAddress((void**)&rlo,  g_real_lo);
    cudaGetSymbolAddress((void**)&ihi,  g_imag_hi);
    cudaGetSymbolAddress((void**)&ilo,  g_imag_lo);
    cudaGetSymbolAddress((void**)&whi,  g_W_hi);
    cudaGetSymbolAddress((void**)&wlo,  g_W_lo);
    cudaGetSymbolAddress((void**)&wohi, g_Wo_hi);
    cudaGetSymbolAddress((void**)&wolo, g_Wo_lo);
    cudaGetSymbolAddress((void**)&ahi,  g_attn_hi);
    cudaGetSymbolAddress((void**)&alo,  g_attn_lo);

    __nv_bfloat16 *qhi, *qlo, *krhi, *krlo, *kihi, *kilo, *vthi, *vtlo, *phi, *plo;
    cudaGetSymbolAddress((void**)&qhi,  g_qhi);
    cudaGetSymbolAddress((void**)&qlo,  g_qlo);
    cudaGetSymbolAddress((void**)&krhi, g_krhi);
    cudaGetSymbolAddress((void**)&krlo, g_krlo);
    cudaGetSymbolAddress((void**)&kihi, g_kihi);
    cudaGetSymbolAddress((void**)&kilo, g_kilo);
    cudaGetSymbolAddress((void**)&vthi, g_vthi);
    cudaGetSymbolAddress((void**)&vtlo, g_vtlo);
    cudaGetSymbolAddress((void**)&phi,  g_phi);
    cudaGetSymbolAddress((void**)&plo,  g_plo);

    float* out = (float*)d_out;

    cudaFuncSetAttribute(mm_bf16x3_kernel,
                         cudaFuncAttributeMaxDynamicSharedMemorySize, 2 * MM_STAGE);
    cudaFuncSetAttribute(scores_mma_kernel,
                         cudaFuncAttributeMaxDynamicSharedMemorySize, 98304);
    cudaFuncSetAttribute(pv_mma_kernel,
                         cudaFuncAttributeMaxDynamicSharedMemorySize, 98304);

    const int SD4 = S * DIM / 4;
    const int DD4 = DIM * DIM / 4;

    // 0) split activations + weights to bf16 hi/lo
    split_kernel<<<(SD4 + 255) / 256, 256>>>(real, rhi, rlo, SD4);
    split_kernel<<<(SD4 + 255) / 256, 256>>>(imag, ihi, ilo, SD4);
    const float* Ws[6] = {Wq_r, Wk_r, Wv_r, Wq_i, Wk_i, Wv_i};
    for (int w = 0; w < 6; w++)
        split_kernel<<<(DD4 + 255) / 256, 256>>>(Ws[w], whi + (size_t)w * DIM * DIM,
                                                 wlo + (size_t)w * DIM * DIM, DD4);
    split_kernel<<<(DD4 + 255) / 256, 256>>>(Wo_r, wohi, wolo, DD4);
    split_kernel<<<(DD4 + 255) / 256, 256>>>(Wo_i, wohi + (size_t)DIM * DIM,
                                             wolo + (size_t)DIM * DIM, DD4);

    // 1) six input projections (mma.sync bf16x3)
    MMArgs gp = {};
    float* outs6[6]      = {qr, kr, vr, qi, ki, vi};
    const float* bs6[6]  = {bq_r, bk_r, bv_r, bq_i, bk_i, bv_i};
    for (int w = 0; w < 6; w++) {
        gp.Ahi[w] = (w < 3) ? rhi : ihi;
        gp.Alo[w] = (w < 3) ? rlo : ilo;
        gp.Bhi[w] = whi + (size_t)w * DIM * DIM;
        gp.Blo[w] = wlo + (size_t)w * DIM * DIM;
        gp.bias[w] = bs6[w];
        gp.C[w]   = outs6[w];
    }
    mm_bf16x3_kernel<<<dim3(DIM / 128, S / 128, 6), 256, 2 * MM_STAGE>>>(gp, S, DIM, DIM);

    // 2) RoPE
    rope_kernel<<<(S * H * 16) / 256, 256>>>(qr, kr, qi, ki, rfreq);

    // 3) V transpose + split
    pack_vt_kernel<<<dim3(S / 64, H), 256>>>(vr, vi, vthi, vtlo);

    // 4) entanglement + phase -> bf16 operand planes
    entangle_kernel<<<S, 256>>>(qr, qi, kr, ki, ent, phase,
                                qhi, qlo, krhi, krlo, kihi, kilo);

    // 5) score magnitudes via tensor cores
    scores_mma_kernel<<<dim3(528, H), 256, 98304>>>(qhi, qlo, krhi, krlo, kihi, kilo,
                                                    s_is, s_at, s_ce, scores);

    // 6) softmax -> bf16 P planes
    softmax_kernel<<<H * S, 256>>>(scores, phi, plo);

    // 7) P·V via tensor cores
    pv_mma_kernel<<<dim3(S / 64, H), 256, 98304>>>(phi, plo, vthi, vtlo, attn);

    // 8) two output projections
    split_kernel<<<(2 * SD4 + 255) / 256, 256>>>(attn, ahi, alo, 2 * SD4);
    MMArgs go = {};
    go.Ahi[0] = ahi;              go.Alo[0] = alo;
    go.Bhi[0] = wohi;             go.Blo[0] = wolo;
    go.bias[0] = bo_r;            go.C[0] = out;
    go.Ahi[1] = ahi + (size_t)S * DIM;  go.Alo[1] = alo + (size_t)S * DIM;
    go.Bhi[1] = wohi + (size_t)DIM * DIM; go.Blo[1] = wolo + (size_t)DIM * DIM;
    go.bias[1] = bo_i;            go.C[1] = out + (size_t)S * DIM;
    mm_bf16x3_kernel<<<dim3(DIM / 128, S / 128, 2), 256, 2 * MM_STAGE>>>(go, S, DIM, DIM);
}

// round 6
// speedup vs baseline: 2.6991x; 1.0009x over previous
#include <cuda_runtime.h>
#include <cuda_bf16.h>
#include <math.h>
#include <stdint.h>

#define S   2048
#define DIM 1024
#define H   16
#define HD  64

#define NEG_INF __int_as_float(0xff800000)

// ---------------- scratch (__device__ globals: allocation-free) ----------------
__device__ float g_qr[S*DIM];
__device__ float g_kr[S*DIM];
__device__ float g_vr[S*DIM];
__device__ float g_qi[S*DIM];
__device__ float g_ki[S*DIM];
__device__ float g_vi[S*DIM];

// bf16 split planes (projection GEMMs)
__device__ __nv_bfloat16 g_real_hi[S*DIM],  g_real_lo[S*DIM];
__device__ __nv_bfloat16 g_imag_hi[S*DIM],  g_imag_lo[S*DIM];
__device__ __nv_bfloat16 g_W_hi[6*DIM*DIM], g_W_lo[6*DIM*DIM];
__device__ __nv_bfloat16 g_Wo_hi[2*DIM*DIM], g_Wo_lo[2*DIM*DIM];
__device__ __nv_bfloat16 g_attn_hi[2*S*DIM], g_attn_lo[2*S*DIM];

// bf16 attention operand planes
__device__ __nv_bfloat16 g_qhi[H*S*128],  g_qlo[H*S*128];   // [h][s][qr|qi]
__device__ __nv_bfloat16 g_krhi[H*S*128], g_krlo[H*S*128];  // [h][s][kr|-ki]
__device__ __nv_bfloat16 g_vthi[H*128*S], g_vtlo[H*128*S];  // [h][n][t]

__device__ __forceinline__ uint32_t smem_to_u32(const void* smem_ptr) {
    uint32_t addr;
    asm("{ .reg .u64 tmp; cvta.to.shared.u64 tmp, %1; cvt.u32.u64 %0, tmp; }"
        : "=r"(addr) : "l"(smem_ptr));
    return addr;
}
__device__ __forceinline__ void ldm_x4(uint32_t* r, uint32_t addr) {
    asm volatile("ldmatrix.sync.aligned.m8n8.x4.shared.b16 {%0,%1,%2,%3}, [%4];"
        : "=r"(r[0]), "=r"(r[1]), "=r"(r[2]), "=r"(r[3]) : "r"(addr));
}
__device__ __forceinline__ void mma_bf16(float* c, const uint32_t* a,
                                         uint32_t b0, uint32_t b1) {
    asm volatile("mma.sync.aligned.m16n8k16.row.col.f32.bf16.bf16.f32 "
        "{%0,%1,%2,%3}, {%4,%5,%6,%7}, {%8,%9}, {%0,%1,%2,%3};"
        : "+f"(c[0]), "+f"(c[1]), "+f"(c[2]), "+f"(c[3])
        : "r"(a[0]), "r"(a[1]), "r"(a[2]), "r"(a[3]), "r"(b0), "r"(b1));
}
__device__ __forceinline__ void cp16(uint32_t dst, const void* src) {
    asm volatile("cp.async.cg.shared.global [%0], [%1], 16;" :: "r"(dst), "l"(src));
}
__device__ __forceinline__ void cp_commit() {
    asm volatile("cp.async.commit_group;" ::: "memory");
}
template<int N> __device__ __forceinline__ void cp_wait() {
    asm volatile("cp.async.wait_group %0;" :: "n"(N) : "memory");
}

// swizzle within a plane of 128B rows (8 chunks of 16B per row)
__device__ __forceinline__ uint32_t swz(int r, int c) {
    return (uint32_t)(r * 128 + ((c ^ (r & 7)) << 4));
}

__device__ __forceinline__ void split_store(__nv_bfloat16* hi, __nv_bfloat16* lo,
                                            size_t o, float v) {
    __nv_bfloat16 h = __float2bfloat16(v);
    hi[o] = h;
    lo[o] = __float2bfloat16(v - __bfloat162float(h));
}

// ---------------- fp32 -> (hi, lo) bf16 split ----------------
__global__ void split_kernel(const float* __restrict__ x,
                             __nv_bfloat16* __restrict__ hi,
                             __nv_bfloat16* __restrict__ lo, int n4)
{
    int i = blockIdx.x * 256 + threadIdx.x;
    if (i >= n4) return;
    float4 v = ((const float4*)x)[i];
    __nv_bfloat16 h0 = __float2bfloat16(v.x);
    __nv_bfloat16 h1 = __float2bfloat16(v.y);
    __nv_bfloat16 h2 = __float2bfloat16(v.z);
    __nv_bfloat16 h3 = __float2bfloat16(v.w);
    __nv_bfloat162 hA; hA.x = h0; hA.y = h1;
    __nv_bfloat162 hB; hB.x = h2; hB.y = h3;
    ((__nv_bfloat162*)hi)[2*i]   = hA;
    ((__nv_bfloat162*)hi)[2*i+1] = hB;
    __nv_bfloat162 lA, lB;
    lA.x = __float2bfloat16(v.x - __bfloat162float(h0));
    lA.y = __float2bfloat16(v.y - __bfloat162float(h1));
    lB.x = __float2bfloat16(v.z - __bfloat162float(h2));
    lB.y = __float2bfloat16(v.w - __bfloat162float(h3));
    ((__nv_bfloat162*)lo)[2*i]   = lA;
    ((__nv_bfloat162*)lo)[2*i+1] = lB;
}

// ---------------- batched mma.sync GEMM: C = A·Bᵀ + bias (bf16x3) ----------------
struct MMArgs {
    const __nv_bfloat16* Ahi[8];
    const __nv_bfloat16* Alo[8];
    const __nv_bfloat16* Bhi[8];
    const __nv_bfloat16* Blo[8];
    const float*         bias[8];
    float*               C[8];
};

#define MM_STAGE 65536u

__global__ __launch_bounds__(256, 1)
void mm_bf16x3_kernel(MMArgs ga, int M, int N, int K)
{
    extern __shared__ __align__(1024) char smem[];
    const int z = blockIdx.z;
    const __nv_bfloat16* __restrict__ Ahi = ga.Ahi[z];
    const __nv_bfloat16* __restrict__ Alo = ga.Alo[z];
    const __nv_bfloat16* __restrict__ Bhi = ga.Bhi[z];
    const __nv_bfloat16* __restrict__ Blo = ga.Blo[z];
    const float* __restrict__ bias = ga.bias[z];
    float* __restrict__       C    = ga.C[z];

    const int m0 = blockIdx.y * 128;
    const int n0 = blockIdx.x * 128;

    const int tid  = threadIdx.x;
    const int lane = tid & 31;
    const int wid  = tid >> 5;
    const int wm   = (wid & 1) * 64;
    const int wn   = (wid >> 1) * 32;

    uint32_t sb = smem_to_u32(smem);

    float acc[4][4][4];
#pragma unroll
    for (int a = 0; a < 4; a++)
#pragma unroll
        for (int b = 0; b < 4; b++)
#pragma unroll
            for (int c = 0; c < 4; c++) acc[a][b][c] = 0.f;

    const int NIT = K / 64;

    auto fill = [&](int it, int buf) {
        int k0 = it * 64;
        uint32_t so = sb + buf * MM_STAGE;
#pragma unroll
        for (int i = 0; i < 4; i++) {
            int q = tid + i * 256;
            int r = q >> 3, c = q & 7;
            uint32_t off = swz(r, c);
            cp16(so +          off, Ahi + (size_t)(m0 + r) * K + k0 + c * 8);
            cp16(so + 16384u + off, Alo + (size_t)(m0 + r) * K + k0 + c * 8);
            cp16(so + 32768u + off, Bhi + (size_t)(n0 + r) * K + k0 + c * 8);
            cp16(so + 49152u + off, Blo + (size_t)(n0 + r) * K + k0 + c * 8);
        }
    };

    fill(0, 0);
    cp_commit();

    for (int it = 0; it < NIT; it++) {
        if (it + 1 < NIT) { fill(it + 1, (it + 1) & 1); cp_commit(); cp_wait<1>(); }
        else              { cp_wait<0>(); }
        __syncthreads();

        uint32_t so = sb + (uint32_t)(it & 1) * MM_STAGE;
#pragma unroll
        for (int kk = 0; kk < 64; kk += 16) {
            int ck = kk >> 3;
            uint32_t ah[4][4], al[4][4];
#pragma unroll
            for (int mt = 0; mt < 4; mt++) {
                int r = wm + mt * 16 + (lane & 15);
                int c = ck + (lane >> 4);
                uint32_t off = swz(r, c);
                ldm_x4(ah[mt], so + off);
                ldm_x4(al[mt], so + 16384u + off);
            }
            uint32_t bh[2][4], bl[2][4];
#pragma unroll
            for (int p = 0; p < 2; p++) {
                int r = wn + p * 16 + (lane & 7) + ((lane >> 4) << 3);
                int c = ck + ((lane >> 3) & 1);
                uint32_t off = swz(r, c);
                ldm_x4(bh[p], so + 32768u + off);
                ldm_x4(bl[p], so + 49152u + off);
            }
#pragma unroll
            for (int mt = 0; mt < 4; mt++)
#pragma unroll
                for (int nt = 0; nt < 4; nt++) {
                    uint32_t b0h = bh[nt >> 1][(nt & 1) * 2];
                    uint32_t b1h = bh[nt >> 1][(nt & 1) * 2 + 1];
                    uint32_t b0l = bl[nt >> 1][(nt & 1) * 2];
                    uint32_t b1l = bl[nt >> 1][(nt & 1) * 2 + 1];
                    mma_bf16(acc[mt][nt], ah[mt], b0h, b1h);
                    mma_bf16(acc[mt][nt], ah[mt], b0l, b1l);
                    mma_bf16(acc[mt][nt], al[mt], b0h, b1h);
                }
        }
        __syncthreads();
    }

#pragma unroll
    for (int mt = 0; mt < 4; mt++) {
        int m = m0 + wm + mt * 16 + (lane >> 2);
#pragma unroll
        for (int nt = 0; nt < 4; nt++) {
            int n = n0 + wn + nt * 8 + (lane & 3) * 2;
            float2 bv = *(const float2*)(bias + n);
            float2 o0, o1;
            o0.x = acc[mt][nt][0] + bv.x;
            o0.y = acc[mt][nt][1] + bv.y;
            o1.x = acc[mt][nt][2] + bv.x;
            o1.y = acc[mt][nt][3] + bv.y;
            *(float2*)(C + (size_t)m * N + n)       = o0;
            *(float2*)(C + (size_t)(m + 8) * N + n) = o1;
        }
    }
}

// ---------------- RoPE (in place on q_r,k_r,q_i,k_i) ----------------
__global__ void rope_kernel(float* q1, float* k1, float* q2, float* k2,
                            const float* __restrict__ freqs)
{
    int idx = blockIdx.x * 256 + threadIdx.x;
    int j  = idx & 15;
    int hh = (idx >> 4) & 15;
    int s  = idx >> 8;
    float ang = (float)s * freqs[j];
    float sn, cs;
    sincosf(ang, &sn, &cs);
    size_t base = (size_t)s * DIM + hh * HD + 2 * j;
    float a, b;
    a = q1[base]; b = q1[base + 1];
    q1[base] = a * cs - b * sn; q1[base + 1] = a * sn + b * cs;
    a = k1[base]; b = k1[base + 1];
    k1[base] = a * cs - b * sn; k1[base + 1] = a * sn + b * cs;
    a = q2[base]; b = q2[base + 1];
    q2[base] = a * cs - b * sn; q2[base + 1] = a * sn + b * cs;
    a = k2[base]; b = k2[base + 1];
    k2[base] = a * cs - b * sn; k2[base + 1] = a * sn + b * cs;
}

// ---------------- V transpose + bf16 split: Vt[h][n=128][t] ----------------
__global__ void pack_vt_kernel(const float* __restrict__ vr,
                               const float* __restrict__ vi,
                               __nv_bfloat16* __restrict__ Vthi,
                               __nv_bfloat16* __restrict__ Vtlo)
{
    int h  = blockIdx.y;
    int t0 = blockIdx.x * 64;
    __shared__ float tr[64][65], tim[64][65];
    int tid = threadIdx.x;
#pragma unroll
    for (int i = 0; i < 16; i++) {
        int q = tid + i * 256;
        int t = q >> 6, c = q & 63;
        tr[t][c]  = vr[(size_t)(t0 + t) * DIM + h * HD + c];
        tim[t][c] = vi[(size_t)(t0 + t) * DIM + h * HD + c];
    }
    __syncthreads();
#pragma unroll
    for (int i = 0; i < 32; i++) {
        int q = tid + i * 256;
        int c = q >> 6, t = q & 63;
        float v = (c < 64) ? tr[t][c] : tim[t][c - 64];
        size_t o = ((size_t)(h * 128 + c)) * S + t0 + t;
        split_store(Vthi, Vtlo, o, v);
    }
}

// ---------------- entanglement + phase -> bf16 hi/lo operands (Q, KR only) -------
__global__ void entangle_kernel(const float* __restrict__ qr, const float* __restrict__ qi,
                                const float* __restrict__ kr, const float* __restrict__ ki,
                                const float* __restrict__ ent, const float* __restrict__ phase,
                                __nv_bfloat16* __restrict__ Qhi, __nv_bfloat16* __restrict__ Qlo,
                                __nv_bfloat16* __restrict__ Rhi, __nv_bfloat16* __restrict__ Rlo)
{
    int s = blockIdx.x;
    __shared__ float sqr[DIM], sqi[DIM], skr[DIM], ski[DIM];
    __shared__ float sent[H * H];
    int tid = threadIdx.x;
    if (tid < H * H) sent[tid] = ent[tid];
    for (int i = tid; i < DIM; i += 256) {
        size_t o = (size_t)s * DIM + i;
        sqr[i] = qr[o]; sqi[i] = qi[o]; skr[i] = kr[o]; ski[i] = ki[o];
    }
    __syncthreads();
    for (int p = tid; p < DIM; p += 256) {
        int x = p >> 6, d = p & 63;
        float aqr = 0.f, aqi = 0.f, akr = 0.f, aki = 0.f;
#pragma unroll
        for (int h2 = 0; h2 < H; h2++) {
            float e = sent[h2 * H + x];
            int o = h2 * HD + d;
            aqr = fmaf(sqr[o], e, aqr);
            aqi = fmaf(sqi[o], e, aqi);
            akr = fmaf(skr[o], e, akr);
            aki = fmaf(ski[o], e, aki);
        }
        float pv = phase[p];
        float ps, pc;
        sincosf(pv, &ps, &pc);
        float qr2 = aqr * pc - aqi * ps;
        float qi2 = aqr * ps + aqi * pc;
        float kr2 = akr * pc - aki * ps;
        float ki2 = akr * ps + aki * pc;
        size_t base = ((size_t)x * S + s) * 128;
        split_store(Qhi, Qlo, base + d,      qr2);
        split_store(Qhi, Qlo, base + HD + d, qi2);
        split_store(Rhi, Rlo, base + d,      kr2);
        split_store(Rhi, Rlo, base + HD + d, -ki2);
    }
}

// ---------------- fused flash attention (scores + softmax + P·V), bf16x3 ----------
// smem: Q hi [0,16K) lo [16K,32K); stage s at 32K + s*64K:
//   KRhi +0, KRlo +16K (each: two 8K sub-planes of 64 cols)
//   Vthi +32K, Vtlo +48K (each: [128 n rows][64 t cols], 16K)
__global__ __launch_bounds__(128, 1)
void fused_attn_kernel(const __nv_bfloat16* __restrict__ Qhi, const __nv_bfloat16* __restrict__ Qlo,
                       const __nv_bfloat16* __restrict__ Rhi, const __nv_bfloat16* __restrict__ Rlo,
                       const __nv_bfloat16* __restrict__ Vthi, const __nv_bfloat16* __restrict__ Vtlo,
                       const float* __restrict__ sc_is, const float* __restrict__ sc_at,
                       const float* __restrict__ sc_ce,
                       __nv_bfloat16* __restrict__ Ahi, __nv_bfloat16* __restrict__ Alo)
{
    extern __shared__ __align__(1024) char smem[];
    const int h  = blockIdx.y;
    const int ti = 31 - blockIdx.x;          // big tiles first
    const int m0 = ti * 64;
    uint32_t sb = smem_to_u32(smem);
    const int tid = threadIdx.x, lane = tid & 31, wid = tid >> 5;
    const int wm = wid * 16;

    // Q fill (once)
#pragma unroll
    for (int pl = 0; pl < 2; pl++) {
        const __nv_bfloat16* sp = (pl ? Qlo : Qhi) + ((size_t)h * S + m0) * 128;
        uint32_t pb = sb + pl * 16384u;
#pragma unroll
        for (int i = 0; i < 8; i++) {
            int q = tid + i * 128;
            int r = q >> 4, cg = q & 15;
            cp16(pb + ((cg & 8) ? 8192u : 0u) + swz(r, cg & 7), sp + (size_t)r * 128 + cg * 8);
        }
    }

    auto fill = [&](int it, int buf) {
        int t0 = it * 64;
        uint32_t so = sb + 32768u + (uint32_t)buf * 65536u;
#pragma unroll
        for (int pl = 0; pl < 2; pl++) {
            const __nv_bfloat16* sp = (pl ? Rlo : Rhi) + ((size_t)h * S + t0) * 128;
            uint32_t pb = so + pl * 16384u;
#pragma unroll
            for (int i = 0; i < 8; i++) {
                int q = tid + i * 128;
                int r = q >> 4, cg = q & 15;
                cp16(pb + ((cg & 8) ? 8192u : 0u) + swz(r, cg & 7), sp + (size_t)r * 128 + cg * 8);
            }
        }
#pragma unroll
        for (int pl = 0; pl < 2; pl++) {
            const __nv_bfloat16* sp = (pl ? Vtlo : Vthi) + (size_t)(h * 128) * S + t0;
            uint32_t pb = so + 32768u + pl * 16384u;
#pragma unroll
            for (int i = 0; i < 8; i++) {
                int q = tid + i * 128;
                int r = q >> 3, c = q & 7;
                cp16(pb + swz(r, c), sp + (size_t)r * S + c * 8);
            }
        }
    };

    fill(0, 0);
    cp_commit();

    float strength = 1.0f / (1.0f + expf(-*sc_is));
    float temp     = fmaxf(expf(*sc_at), 0.1f);
    float eps      = 0.03f / (1.0f + expf(-*sc_ce));
    float factor   = strength / temp;

    float outacc[16][4];
#pragma unroll
    for (int a = 0; a < 16; a++)
#pragma unroll
        for (int c = 0; c < 4; c++) outacc[a][c] = 0.f;
    float M2[2] = {NEG_INF, NEG_INF};
    float L2[2] = {0.f, 0.f};

    const int rowA = m0 + wm + (lane >> 2);
    const int rowB = rowA + 8;
    const int nit  = ti + 1;

    for (int it = 0; it < nit; it++) {
        if (it + 1 < nit) { fill(it + 1, (it + 1) & 1); cp_commit(); cp_wait<1>(); }
        else              { cp_wait<0>(); }
        __syncthreads();
        uint32_t so = sb + 32768u + (uint32_t)(it & 1) * 65536u;

        // ---- scores: accr = Q·KRᵀ, acci = Q·KIᵀ with KI derived from KR ----
        float accr[8][4], acci[8][4];
#pragma unroll
        for (int a = 0; a < 8; a++)
#pragma unroll
            for (int c = 0; c < 4; c++) { accr[a][c] = 0.f; acci[a][c] = 0.f; }

#pragma unroll
        for (int ckp = 0; ckp < 8; ckp += 2) {
            uint32_t ahL[4], alL[4], ahU[4], alU[4];
            {
                int r = wm + (lane & 15);
                int cg = ckp + (lane >> 4);          // 0..7
                uint32_t offL = swz(r, cg);
                uint32_t offU = 8192u + swz(r, cg);  // chunk cg+8
                ldm_x4(ahL, sb + offL);
                ldm_x4(alL, sb + 16384u + offL);
                ldm_x4(ahU, sb + offU);
                ldm_x4(alU, sb + 16384u + offU);
            }
#pragma unroll
            for (int p = 0; p < 4; p++) {
                int r = p * 16 + (lane & 7) + ((lane >> 4) << 3);
                int cg = ckp + ((lane >> 3) & 1);
                uint32_t offL = swz(r, cg);
                uint32_t offU = 8192u + swz(r, cg);
                uint32_t bhL[4], blL[4], bhU[4], blU[4];
                ldm_x4(bhL, so + offL);
                ldm_x4(blL, so + 16384u + offL);
                ldm_x4(bhU, so + offU);
                ldm_x4(blU, so + 16384u + offU);
#pragma unroll
                for (int e2 = 0; e2 < 2; e2++) {
                    int nt = p * 2 + e2, e = e2 * 2;
                    mma_bf16(accr[nt], ahL, bhL[e], bhL[e + 1]);
                    mma_bf16(accr[nt], ahL, blL[e], blL[e + 1]);
                    mma_bf16(accr[nt], alL, bhL[e], bhL[e + 1]);
                    mma_bf16(accr[nt], ahU, bhU[e], bhU[e + 1]);
                    mma_bf16(accr[nt], ahU, blU[e], blU[e + 1]);
                    mma_bf16(accr[nt], alU, bhU[e], bhU[e + 1]);
                    // imag upper-k: Q_U · KR_L  (KI upper half == kr)
                    mma_bf16(acci[nt], ahU, bhL[e], bhL[e + 1]);
                    mma_bf16(acci[nt], ahU, blL[e], blL[e + 1]);
                    mma_bf16(acci[nt], alU, bhL[e], bhL[e + 1]);
                }
                // imag lower-k: Q_L · (−KR_U)  (KI lower half == ki == −KR_U)
#pragma unroll
                for (int x = 0; x < 4; x++) { bhU[x] ^= 0x80008000u; blU[x] ^= 0x80008000u; }
#pragma unroll
                for (int e2 = 0; e2 < 2; e2++) {
                    int nt = p * 2 + e2, e = e2 * 2;
                    mma_bf16(acci[nt], ahL, bhU[e], bhU[e + 1]);
                    mma_bf16(acci[nt], ahL, blU[e], blU[e + 1]);
                    mma_bf16(acci[nt], alL, bhU[e], bhU[e + 1]);
                }
            }
        }

        // ---- magnitude + causal mask ----
        int t0 = it * 64;
#pragma unroll
        for (int nt = 0; nt < 8; nt++) {
            int cbase = t0 + nt * 8 + (lane & 3) * 2;
#pragma unroll
            for (int j = 0; j < 4; j++) {
                float r  = accr[nt][j] * 0.125f;
                float im = acci[nt][j] * 0.125f;
                float ar = r + eps * im;
                float ai = im - eps * r;
                float m  = sqrtf(ar * ar + ai * ai + 1e-6f) * factor;
                int col = cbase + (j & 1);
                int row = (j < 2) ? rowA : rowB;
                accr[nt][j] = (col <= row) ? m : NEG_INF;
            }
        }

        // ---- online softmax ----
        float mxA = NEG_INF, mxB = NEG_INF;
#pragma unroll
        for (int nt = 0; nt < 8; nt++) {
            mxA = fmaxf(mxA, fmaxf(accr[nt][0], accr[nt][1]));
            mxB = fmaxf(mxB, fmaxf(accr[nt][2], accr[nt][3]));
        }
        mxA = fmaxf(mxA, __shfl_xor_sync(0xffffffffu, mxA, 1));
        mxA = fmaxf(mxA, __shfl_xor_sync(0xffffffffu, mxA, 2));
        mxB = fmaxf(mxB, __shfl_xor_sync(0xffffffffu, mxB, 1));
        mxB = fmaxf(mxB, __shfl_xor_sync(0xffffffffu, mxB, 2));
        float MnA = fmaxf(M2[0], mxA), MnB = fmaxf(M2[1], mxB);
        float scA = __expf(M2[0] - MnA), scB = __expf(M2[1] - MnB);
        M2[0] = MnA; M2[1] = MnB;

        float sA = 0.f, sB = 0.f;
        uint32_t pfh[4][4], pfl[4][4];
#pragma unroll
        for (int nt = 0; nt < 8; nt++) {
            float p0 = __expf(accr[nt][0] - MnA);
            float p1 = __expf(accr[nt][1] - MnA);
            float p2 = __expf(accr[nt][2] - MnB);
            float p3 = __expf(accr[nt][3] - MnB);
            sA += p0 + p1; sB += p2 + p3;
            __nv_bfloat162 h01, l01, h23, l23;
            h01.x = __float2bfloat16(p0); h01.y = __float2bfloat16(p1);
            l01.x = __float2bfloat16(p0 - __bfloat162float(h01.x));
            l01.y = __float2bfloat16(p1 - __bfloat162float(h01.y));
            h23.x = __float2bfloat16(p2); h23.y = __float2bfloat16(p3);
            l23.x = __float2bfloat16(p2 - __bfloat162float(h23.x));
            l23.y = __float2bfloat16(p3 - __bfloat162float(h23.y));
            int kk = nt >> 1, sel = (nt & 1) * 2;
            pfh[kk][sel]     = *(uint32_t*)&h01;
            pfh[kk][sel + 1] = *(uint32_t*)&h23;
            pfl[kk][sel]     = *(uint32_t*)&l01;
            pfl[kk][sel + 1] = *(uint32_t*)&l23;
        }
        sA += __shfl_xor_sync(0xffffffffu, sA, 1);
        sA += __shfl_xor_sync(0xffffffffu, sA, 2);
        sB += __shfl_xor_sync(0xffffffffu, sB, 1);
        sB += __shfl_xor_sync(0xffffffffu, sB, 2);
        L2[0] = L2[0] * scA + sA;
        L2[1] = L2[1] * scB + sB;

#pragma unroll
        for (int nt2 = 0; nt2 < 16; nt2++) {
            outacc[nt2][0] *= scA; outacc[nt2][1] *= scA;
            outacc[nt2][2] *= scB; outacc[nt2][3] *= scB;
        }

        // ---- P · V ----
        uint32_t vbase = so + 32768u;
#pragma unroll
        for (int kk = 0; kk < 4; kk++) {
#pragma unroll
            for (int p2 = 0; p2 < 8; p2++) {
                int r = p2 * 16 + (lane & 7) + ((lane >> 4) << 3);
                int cg = kk * 2 + ((lane >> 3) & 1);
                uint32_t off = swz(r, cg);
                uint32_t vh[4], vl[4];
                ldm_x4(vh, vbase + off);
                ldm_x4(vl, vbase + 16384u + off);
#pragma unroll
                for (int e2 = 0; e2 < 2; e2++) {
                    int nt2 = p2 * 2 + e2, e = e2 * 2;
                    mma_bf16(outacc[nt2], pfh[kk], vh[e], vh[e + 1]);
                    mma_bf16(outacc[nt2], pfh[kk], vl[e], vl[e + 1]);
                    mma_bf16(outacc[nt2], pfl[kk], vh[e], vh[e + 1]);
                }
            }
        }
        __syncthreads();
    }

    // ---- epilogue: normalize, write bf16 hi/lo attn planes ----
    float invA = 1.0f / L2[0], invB = 1.0f / L2[1];
#pragma unroll
    for (int nt2 = 0; nt2 < 16; nt2++) {
        int col = nt2 * 8 + (lane & 3) * 2;
        size_t pofs = (col < HD) ? 0 : (size_t)S * DIM;
        int d0 = col & 63;
        size_t bA = pofs + (size_t)rowA * DIM + h * HD + d0;
        size_t bB = pofs + (size_t)rowB * DIM + h * HD + d0;
        split_store(Ahi, Alo, bA,     outacc[nt2][0] * invA);
        split_store(Ahi, Alo, bA + 1, outacc[nt2][1] * invA);
        split_store(Ahi, Alo, bB,     outacc[nt2][2] * invB);
        split_store(Ahi, Alo, bB + 1, outacc[nt2][3] * invB);
    }
}

// ---------------- host ----------------
extern "C" void kernel_launch(void* const* d_in, const int* in_sizes, int n_in,
                              void* d_out, int out_size)
{
    const float* real  = (const float*)d_in[0];
    const float* imag  = (const float*)d_in[1];
    const float* Wq_r  = (const float*)d_in[2];
    const float* bq_r  = (const float*)d_in[3];
    const float* Wk_r  = (const float*)d_in[4];
    const float* bk_r  = (const float*)d_in[5];
    const float* Wv_r  = (const float*)d_in[6];
    const float* bv_r  = (const float*)d_in[7];
    const float* Wq_i  = (const float*)d_in[8];
    const float* bq_i  = (const float*)d_in[9];
    const float* Wk_i  = (const float*)d_in[10];
    const float* bk_i  = (const float*)d_in[11];
    const float* Wv_i  = (const float*)d_in[12];
    const float* bv_i  = (const float*)d_in[13];
    const float* Wo_r  = (const float*)d_in[14];
    const float* bo_r  = (const float*)d_in[15];
    const float* Wo_i  = (const float*)d_in[16];
    const float* bo_i  = (const float*)d_in[17];
    const float* phase = (const float*)d_in[18];
    const float* ent   = (const float*)d_in[19];
    const float* rfreq = (const float*)d_in[20];
    const float* s_is  = (const float*)d_in[21];
    const float* s_at  = (const float*)d_in[22];
    const float* s_ce  = (const float*)d_in[23];

    float *qr, *kr, *vr, *qi, *ki, *vi;
    cudaGetSymbolAddress((void**)&qr, g_qr);
    cudaGetSymbolAddress((void**)&kr, g_kr);
    cudaGetSymbolAddress((void**)&vr, g_vr);
    cudaGetSymbolAddress((void**)&qi, g_qi);
    cudaGetSymbolAddress((void**)&ki, g_ki);
    cudaGetSymbolAddress((void**)&vi, g_vi);

    __nv_bfloat16 *rhi, *rlo, *ihi, *ilo, *whi, *wlo, *wohi, *wolo, *ahi, *alo;
    cudaGetSymbolAddress((void**)&rhi,  g_real_hi);
    cudaGetSymbolAddress((void**)&rlo,  g_real_lo);
    cudaGetSymbolAddress((void**)&ihi,  g_imag_hi);
    cudaGetSymbolAddress((void**)&ilo,  g_imag_lo);
    cudaGetSymbolAddress((void**)&whi,  g_W_hi);
    cudaGetSymbolAddress((void**)&wlo,  g_W_lo);
    cudaGetSymbolAddress((void**)&wohi, g_Wo_hi);
    cudaGetSymbolAddress((void**)&wolo, g_Wo_lo);
    cudaGetSymbolAddress((void**)&ahi,  g_attn_hi);
    cudaGetSymbolAddress((void**)&alo,  g_attn_lo);

    __nv_bfloat16 *qhi, *qlo, *krhi, *krlo, *vthi, *vtlo;
    cudaGetSymbolAddress((void**)&qhi,  g_qhi);
    cudaGetSymbolAddress((void**)&qlo,  g_qlo);
    cudaGetSymbolAddress((void**)&krhi, g_krhi);
    cudaGetSymbolAddress((void**)&krlo, g_krlo);
    cudaGetSymbolAddress((void**)&vthi, g_vthi);
    cudaGetSymbolAddress((void**)&vtlo, g_vtlo);

    float* out = (float*)d_out;

    cudaFuncSetAttribute(mm_bf16x3_kernel,
                         cudaFuncAttributeMaxDynamicSharedMemorySize, 2 * MM_STAGE);
    cudaFuncSetAttribute(fused_attn_kernel,
                         cudaFuncAttributeMaxDynamicSharedMemorySize, 163840);

    const int SD4 = S * DIM / 4;
    const int DD4 = DIM * DIM / 4;

    // 0) split activations + weights to bf16 hi/lo
    split_kernel<<<(SD4 + 255) / 256, 256>>>(real, rhi, rlo, SD4);
    split_kernel<<<(SD4 + 255) / 256, 256>>>(imag, ihi, ilo, SD4);
    const float* Ws[6] = {Wq_r, Wk_r, Wv_r, Wq_i, Wk_i, Wv_i};
    for (int w = 0; w < 6; w++)
        split_kernel<<<(DD4 + 255) / 256, 256>>>(Ws[w], whi + (size_t)w * DIM * DIM,
                                                 wlo + (size_t)w * DIM * DIM, DD4);
    split_kernel<<<(DD4 + 255) / 256, 256>>>(Wo_r, wohi, wolo, DD4);
    split_kernel<<<(DD4 + 255) / 256, 256>>>(Wo_i, wohi + (size_t)DIM * DIM,
                                             wolo + (size_t)DIM * DIM, DD4);

    // 1) six input projections (mma.sync bf16x3)
    MMArgs gp = {};
    float* outs6[6]      = {qr, kr, vr, qi, ki, vi};
    const float* bs6[6]  = {bq_r, bk_r, bv_r, bq_i, bk_i, bv_i};
    for (int w = 0; w < 6; w++) {
        gp.Ahi[w] = (w < 3) ? rhi : ihi;
        gp.Alo[w] = (w < 3) ? rlo : ilo;
        gp.Bhi[w] = whi + (size_t)w * DIM * DIM;
        gp.Blo[w] = wlo + (size_t)w * DIM * DIM;
        gp.bias[w] = bs6[w];
        gp.C[w]   = outs6[w];
    }
    mm_bf16x3_kernel<<<dim3(DIM / 128, S / 128, 6), 256, 2 * MM_STAGE>>>(gp, S, DIM, DIM);

    // 2) RoPE
    rope_kernel<<<(S * H * 16) / 256, 256>>>(qr, kr, qi, ki, rfreq);

    // 3) V transpose + split
    pack_vt_kernel<<<dim3(S / 64, H), 256>>>(vr, vi, vthi, vtlo);

    // 4) entanglement + phase -> Q, KR bf16 planes
    entangle_kernel<<<S, 256>>>(qr, qi, kr, ki, ent, phase, qhi, qlo, krhi, krlo);

    // 5) fused attention (scores + online softmax + P·V) -> bf16 attn planes
    fused_attn_kernel<<<dim3(32, H), 128, 163840>>>(qhi, qlo, krhi, krlo, vthi, vtlo,
                                                    s_is, s_at, s_ce, ahi, alo);

    // 6) two output projections
    MMArgs go = {};
    go.Ahi[0] = ahi;              go.Alo[0] = alo;
    go.Bhi[0] = wohi;             go.Blo[0] = wolo;
    go.bias[0] = bo_r;            go.C[0] = out;
    go.Ahi[1] = ahi + (size_t)S * DIM;  go.Alo[1] = alo + (size_t)S * DIM;
    go.Bhi[1] = wohi + (size_t)DIM * DIM; go.Blo[1] = wolo + (size_t)DIM * DIM;
    go.bias[1] = bo_i;            go.C[1] = out + (size_t)S * DIM;
    mm_bf16x3_kernel<<<dim3(DIM / 128, S / 128, 2), 256, 2 * MM_STAGE>>>(go, S, DIM, DIM);
}